// round 1
// baseline (speedup 1.0000x reference)
#include <cuda_runtime.h>
#include <cuda_bf16.h>
#include <math.h>

// Problem constants: x [Bs=2, M=32, T=1024, C=768], N_HEADS=12, D=64
// Rows R = 64*1024 = 65536, "bm" = flattened (b,m) in [0,64)
#define NBM   64
#define TT    1024
#define CC    768
#define NH    12
#define DD    64
#define EPSV  1e-6f

// ---- scratch (device globals; allocation-free contract) ----
__device__ float g_kk  [NBM * NH * TT];          // kk[bm,n,t] = sum_d k
__device__ float g_kpart[NBM * NH * 8 * DD];     // per-rowtile partial ksum
__device__ float g_ksum[NBM * NH * DD];          // ksum[bm,n,d]
__device__ float g_u   [NBM * NH * CC];          // u[bm,n,c] = sum_t kk*x
__device__ float g_z   [NBM * NH * TT];          // z[bm,n,t]
__device__ float g_ws  [NBM * NH * CC];          // ws[bm,n,j]

// ============================================================
// Projection GEMM: y[r, c0..c0+63] = x[r,:] @ w[c,:]^T + b[c]
// tile: BM=128 rows x BN=64 cols (one head) x BK=16, 256 threads,
// 8x4 micro-tile. mode 0 (K): epilogue -> kk, ksum partials.
// mode 1 (Q): epilogue -> z = 1/(q . ksum + eps). Never stores y.
// ============================================================
__global__ __launch_bounds__(256) void proj_kernel(
    const float* __restrict__ x, const float* __restrict__ w,
    const float* __restrict__ bias, int mode)
{
    __shared__ float As[2][16][128];
    __shared__ float Bsh[2][16][64];
    __shared__ float red[128][17];
    __shared__ float cred[64][17];

    const int tid    = threadIdx.x;
    const int n      = blockIdx.x;          // head index
    const int by     = blockIdx.y;          // row tile (512 total)
    const int bm     = by >> 3;
    const int tile8  = by & 7;
    const int t0     = tile8 << 7;
    const int r0     = by << 7;
    const int c0     = n << 6;
    const int colgrp = tid & 15;
    const int rowgrp = tid >> 4;
    const int h      = bm * NH + n;

    const float* Abase = x + (size_t)r0 * CC;
    const float* Bbase = w + (size_t)c0 * CC;

    float acc[8][4];
    #pragma unroll
    for (int i = 0; i < 8; i++)
        #pragma unroll
        for (int j = 0; j < 4; j++) acc[i][j] = 0.f;

    // A-load mapping: each thread loads 8 contiguous k-floats of one row
    const int arow  = tid >> 1;
    const int kbase = (tid & 1) * 8;
    // B-load mapping: each thread loads 4 k-floats of one w-row
    const int brow = tid >> 2;
    const int bkq  = (tid & 3) * 4;

    float4 ra0, ra1, rb0;

    // prologue: chunk 0
    ra0 = *(const float4*)(Abase + (size_t)arow * CC + kbase);
    ra1 = *(const float4*)(Abase + (size_t)arow * CC + kbase + 4);
    rb0 = *(const float4*)(Bbase + (size_t)brow * CC + bkq);
    {
        As[0][kbase + 0][arow] = ra0.x; As[0][kbase + 1][arow] = ra0.y;
        As[0][kbase + 2][arow] = ra0.z; As[0][kbase + 3][arow] = ra0.w;
        As[0][kbase + 4][arow] = ra1.x; As[0][kbase + 5][arow] = ra1.y;
        As[0][kbase + 6][arow] = ra1.z; As[0][kbase + 7][arow] = ra1.w;
        Bsh[0][bkq + 0][brow] = rb0.x; Bsh[0][bkq + 1][brow] = rb0.y;
        Bsh[0][bkq + 2][brow] = rb0.z; Bsh[0][bkq + 3][brow] = rb0.w;
    }
    __syncthreads();

    int cur = 0;
    for (int ch = 0; ch < 48; ch++) {
        const bool more = (ch + 1) < 48;
        if (more) {
            const int kc = (ch + 1) * 16;
            ra0 = *(const float4*)(Abase + (size_t)arow * CC + kc + kbase);
            ra1 = *(const float4*)(Abase + (size_t)arow * CC + kc + kbase + 4);
            rb0 = *(const float4*)(Bbase + (size_t)brow * CC + kc + bkq);
        }
        #pragma unroll
        for (int k = 0; k < 16; k++) {
            float4 aLo = *(const float4*)&As[cur][k][rowgrp * 8];
            float4 aHi = *(const float4*)&As[cur][k][rowgrp * 8 + 4];
            float4 bb  = *(const float4*)&Bsh[cur][k][colgrp * 4];
            float a[8] = {aLo.x, aLo.y, aLo.z, aLo.w, aHi.x, aHi.y, aHi.z, aHi.w};
            float bv[4] = {bb.x, bb.y, bb.z, bb.w};
            #pragma unroll
            for (int i = 0; i < 8; i++)
                #pragma unroll
                for (int j = 0; j < 4; j++)
                    acc[i][j] = fmaf(a[i], bv[j], acc[i][j]);
        }
        if (more) {
            const int nxt = cur ^ 1;
            As[nxt][kbase + 0][arow] = ra0.x; As[nxt][kbase + 1][arow] = ra0.y;
            As[nxt][kbase + 2][arow] = ra0.z; As[nxt][kbase + 3][arow] = ra0.w;
            As[nxt][kbase + 4][arow] = ra1.x; As[nxt][kbase + 5][arow] = ra1.y;
            As[nxt][kbase + 6][arow] = ra1.z; As[nxt][kbase + 7][arow] = ra1.w;
            Bsh[nxt][bkq + 0][brow] = rb0.x; Bsh[nxt][bkq + 1][brow] = rb0.y;
            Bsh[nxt][bkq + 2][brow] = rb0.z; Bsh[nxt][bkq + 3][brow] = rb0.w;
            __syncthreads();
            cur = nxt;
        }
    }

    // bias + elu(.)+1
    float bvv[4];
    #pragma unroll
    for (int j = 0; j < 4; j++) bvv[j] = bias[c0 + colgrp * 4 + j];
    float v[8][4];
    #pragma unroll
    for (int i = 0; i < 8; i++)
        #pragma unroll
        for (int j = 0; j < 4; j++) {
            float pre = acc[i][j] + bvv[j];
            v[i][j] = (pre > 0.f) ? (pre + 1.f) : expf(pre);
        }

    if (mode == 0) {
        // ---- K mode: kk (row sums) + ksum partial (col sums) ----
        #pragma unroll
        for (int i = 0; i < 8; i++)
            red[rowgrp * 8 + i][colgrp] = v[i][0] + v[i][1] + v[i][2] + v[i][3];
        __syncthreads();
        if (tid < 128) {
            float s = 0.f;
            #pragma unroll
            for (int g = 0; g < 16; g++) s += red[tid][g];
            g_kk[(size_t)h * TT + t0 + tid] = s;
        }
        float cs[4];
        #pragma unroll
        for (int j = 0; j < 4; j++) {
            float s = 0.f;
            #pragma unroll
            for (int i = 0; i < 8; i++) s += v[i][j];
            cs[j] = s;
        }
        #pragma unroll
        for (int j = 0; j < 4; j++)
            cred[colgrp * 4 + j][rowgrp] = cs[j];
        __syncthreads();
        if (tid < 64) {
            float s = 0.f;
            #pragma unroll
            for (int g = 0; g < 16; g++) s += cred[tid][g];
            g_kpart[((size_t)h * 8 + tile8) * DD + tid] = s;
        }
    } else {
        // ---- Q mode: z = 1 / (q . ksum + eps) ----
        float4 ksv = *(const float4*)&g_ksum[(size_t)h * DD + colgrp * 4];
        float ks[4] = {ksv.x, ksv.y, ksv.z, ksv.w};
        #pragma unroll
        for (int i = 0; i < 8; i++) {
            float zp = v[i][0] * ks[0] + v[i][1] * ks[1] + v[i][2] * ks[2] + v[i][3] * ks[3];
            red[rowgrp * 8 + i][colgrp] = zp;
        }
        __syncthreads();
        if (tid < 128) {
            float s = 0.f;
            #pragma unroll
            for (int g = 0; g < 16; g++) s += red[tid][g];
            g_z[(size_t)h * TT + t0 + tid] = 1.f / (s + EPSV);
        }
    }
}

// ---- sum the 8 per-rowtile partials into ksum (deterministic, no atomics) ----
__global__ void reduce_ksum_kernel()
{
    int idx = blockIdx.x * blockDim.x + threadIdx.x;
    if (idx < NBM * NH * DD) {
        int hh = idx >> 6;
        int d  = idx & 63;
        float s = 0.f;
        #pragma unroll
        for (int p = 0; p < 8; p++)
            s += g_kpart[((size_t)hh * 8 + p) * DD + d];
        g_ksum[idx] = s;
    }
}

// ---- u[bm,n,c] = sum_t kk[bm,n,t] * x[bm,t,c]  (single x pass) ----
__global__ __launch_bounds__(128) void u_kernel(const float* __restrict__ x)
{
    __shared__ float skk[NH][TT];
    const int bm = blockIdx.y;
    const int c0 = blockIdx.x * 128;
    const int tid = threadIdx.x;
    for (int idx = tid; idx < NH * TT; idx += 128)
        skk[idx >> 10][idx & 1023] = g_kk[(size_t)bm * NH * TT + idx];
    __syncthreads();

    float acc[NH];
    #pragma unroll
    for (int nn = 0; nn < NH; nn++) acc[nn] = 0.f;
    const float* xp = x + (size_t)bm * TT * CC + c0 + tid;
    for (int t = 0; t < TT; t += 2) {
        float x0 = xp[(size_t)t * CC];
        float x1 = xp[(size_t)(t + 1) * CC];
        #pragma unroll
        for (int nn = 0; nn < NH; nn++) {
            float2 kp = *(const float2*)&skk[nn][t];
            acc[nn] = fmaf(kp.x, x0, fmaf(kp.y, x1, acc[nn]));
        }
    }
    #pragma unroll
    for (int nn = 0; nn < NH; nn++)
        g_u[((size_t)bm * NH + nn) * CC + c0 + tid] = acc[nn];
}

// ---- s[n,e] = u[n,:].wv_row + bv*Kt ;  ws[n,j] = sum_e s[n,e]*wp[j,nD+e] ----
__global__ __launch_bounds__(256) void sws_kernel(
    const float* __restrict__ wv, const float* __restrict__ bv,
    const float* __restrict__ wp)
{
    __shared__ float ss[CC];
    __shared__ float sKt[NH];
    const int bm = blockIdx.x;
    const int tid = threadIdx.x;
    if (tid < NH) {
        float s = 0.f;
        #pragma unroll
        for (int d = 0; d < DD; d++)
            s += g_ksum[((size_t)bm * NH + tid) * DD + d];
        sKt[tid] = s;
    }
    __syncthreads();
    for (int idx = tid; idx < CC; idx += 256) {
        int nn = idx >> 6;
        const float* up = g_u + ((size_t)bm * NH + nn) * CC;
        const float* wr = wv + (size_t)idx * CC;
        float dot = 0.f;
        for (int i = 0; i < CC; i += 4) {
            float4 uu = *(const float4*)(up + i);
            float4 ww = *(const float4*)(wr + i);
            dot += uu.x * ww.x + uu.y * ww.y + uu.z * ww.z + uu.w * ww.w;
        }
        ss[idx] = dot + bv[idx] * sKt[nn];
    }
    __syncthreads();
    for (int idx = tid; idx < NH * CC; idx += 256) {
        int nn = idx / CC;
        int jc = idx - nn * CC;
        const float* sp = ss + nn * DD;
        const float* wr = wp + (size_t)jc * CC + nn * DD;
        float dot = 0.f;
        #pragma unroll
        for (int e = 0; e < DD; e += 4) {
            float4 s4 = *(const float4*)(sp + e);
            float4 w4 = *(const float4*)(wr + e);
            dot += s4.x * w4.x + s4.y * w4.y + s4.z * w4.z + s4.w * w4.w;
        }
        g_ws[((size_t)bm * NH + nn) * CC + jc] = dot;
    }
}

// ---- out[bm,t,j] = sum_n z[n,t] * ws[n,j] + bp[j] ----
__global__ __launch_bounds__(256) void out_kernel(
    const float* __restrict__ bp, float* __restrict__ out)
{
    __shared__ float sws[NH][CC];
    __shared__ float sbp[CC];
    __shared__ float sz[NH][64];
    const int bm  = blockIdx.y;
    const int tr0 = blockIdx.x * 64;
    const int tid = threadIdx.x;
    for (int idx = tid; idx < NH * CC; idx += 256)
        sws[idx / CC][idx % CC] = g_ws[(size_t)bm * NH * CC + idx];
    for (int idx = tid; idx < CC; idx += 256) sbp[idx] = bp[idx];
    for (int idx = tid; idx < NH * 64; idx += 256)
        sz[idx >> 6][idx & 63] =
            g_z[((size_t)bm * NH + (idx >> 6)) * TT + tr0 + (idx & 63)];
    __syncthreads();

    for (int tt = 0; tt < 64; tt++) {
        float z[NH];
        #pragma unroll
        for (int nn = 0; nn < NH; nn++) z[nn] = sz[nn][tt];
        size_t ob = ((size_t)bm * TT + tr0 + tt) * CC;
        for (int cc = tid; cc < CC; cc += 256) {
            float a = sbp[cc];
            #pragma unroll
            for (int nn = 0; nn < NH; nn++)
                a = fmaf(z[nn], sws[nn][cc], a);
            out[ob + cc] = a;
        }
    }
}

extern "C" void kernel_launch(void* const* d_in, const int* in_sizes, int n_in,
                              void* d_out, int out_size)
{
    const float* x  = (const float*)d_in[0];
    const float* wq = (const float*)d_in[1];
    const float* bq = (const float*)d_in[2];
    const float* wk = (const float*)d_in[3];
    const float* bk = (const float*)d_in[4];
    const float* wv = (const float*)d_in[5];
    const float* bv = (const float*)d_in[6];
    const float* wp = (const float*)d_in[7];
    const float* bp = (const float*)d_in[8];
    float* out = (float*)d_out;

    dim3 pg(NH, 512);
    proj_kernel<<<pg, 256>>>(x, wk, bk, 0);                 // K proj + kk/ksum partials
    reduce_ksum_kernel<<<(NBM * NH * DD + 255) / 256, 256>>>();
    u_kernel<<<dim3(6, NBM), 128>>>(x);                     // u = kk-weighted x sums
    sws_kernel<<<NBM, 256>>>(wv, bv, wp);                   // s and ws (tiny GEMMs)
    proj_kernel<<<pg, 256>>>(x, wq, bq, 1);                 // Q proj -> z directly
    out_kernel<<<dim3(16, NBM), 256>>>(bp, out);            // rank-12 output update
}

// round 4
// speedup vs baseline: 1.0007x; 1.0007x over previous
#include <cuda_runtime.h>
#include <cuda_bf16.h>
#include <math.h>

// Problem constants: x [Bs=2, M=32, T=1024, C=768], N_HEADS=12, D=64
// Rows R = 64*1024 = 65536, "bm" = flattened (b,m) in [0,64)
#define NBM   64
#define TT    1024
#define CC    768
#define NH    12
#define DD    64
#define EPSV  1e-6f

// ---- scratch (device globals; allocation-free contract) ----
__device__ float g_kk  [NBM * NH * TT];          // kk[bm,n,t] = sum_d k
__device__ float g_kpart[NBM * NH * 8 * DD];     // per-rowtile partial ksum
__device__ float g_ksum[NBM * NH * DD];          // ksum[bm,n,d]
__device__ float g_u   [NBM * NH * CC];          // u[bm,n,c] = sum_t kk*x
__device__ float g_z   [NBM * NH * TT];          // z[bm,n,t]
__device__ float g_ws  [NBM * NH * CC];          // ws[bm,n,j]

// ============================================================
// Projection GEMM: y[r, c0..c0+63] = x[r,:] @ w[c,:]^T + b[c]
// tile: BM=128 rows x BN=64 cols (one head) x BK=16, 256 threads,
// 8x4 micro-tile. mode 0 (K): epilogue -> kk, ksum partials.
// mode 1 (Q): epilogue -> z = 1/(q . ksum + eps). Never stores y.
// ============================================================
__global__ __launch_bounds__(256) void proj_kernel(
    const float* __restrict__ x, const float* __restrict__ w,
    const float* __restrict__ bias, int mode)
{
    __shared__ float As[2][16][128];
    __shared__ float Bsh[2][16][64];
    __shared__ float red[128][17];
    __shared__ float cred[64][17];

    const int tid    = threadIdx.x;
    const int n      = blockIdx.x;          // head index
    const int by     = blockIdx.y;          // row tile (512 total)
    const int bm     = by >> 3;
    const int tile8  = by & 7;
    const int t0     = tile8 << 7;
    const int r0     = by << 7;
    const int c0     = n << 6;
    const int colgrp = tid & 15;
    const int rowgrp = tid >> 4;
    const int h      = bm * NH + n;

    const float* Abase = x + (size_t)r0 * CC;
    const float* Bbase = w + (size_t)c0 * CC;

    float acc[8][4];
    #pragma unroll
    for (int i = 0; i < 8; i++)
        #pragma unroll
        for (int j = 0; j < 4; j++) acc[i][j] = 0.f;

    // A-load mapping: each thread loads 8 contiguous k-floats of one row
    const int arow  = tid >> 1;
    const int kbase = (tid & 1) * 8;
    // B-load mapping: each thread loads 4 k-floats of one w-row
    const int brow = tid >> 2;
    const int bkq  = (tid & 3) * 4;

    float4 ra0, ra1, rb0;

    // prologue: chunk 0
    ra0 = *(const float4*)(Abase + (size_t)arow * CC + kbase);
    ra1 = *(const float4*)(Abase + (size_t)arow * CC + kbase + 4);
    rb0 = *(const float4*)(Bbase + (size_t)brow * CC + bkq);
    {
        As[0][kbase + 0][arow] = ra0.x; As[0][kbase + 1][arow] = ra0.y;
        As[0][kbase + 2][arow] = ra0.z; As[0][kbase + 3][arow] = ra0.w;
        As[0][kbase + 4][arow] = ra1.x; As[0][kbase + 5][arow] = ra1.y;
        As[0][kbase + 6][arow] = ra1.z; As[0][kbase + 7][arow] = ra1.w;
        Bsh[0][bkq + 0][brow] = rb0.x; Bsh[0][bkq + 1][brow] = rb0.y;
        Bsh[0][bkq + 2][brow] = rb0.z; Bsh[0][bkq + 3][brow] = rb0.w;
    }
    __syncthreads();

    int cur = 0;
    for (int ch = 0; ch < 48; ch++) {
        const bool more = (ch + 1) < 48;
        if (more) {
            const int kc = (ch + 1) * 16;
            ra0 = *(const float4*)(Abase + (size_t)arow * CC + kc + kbase);
            ra1 = *(const float4*)(Abase + (size_t)arow * CC + kc + kbase + 4);
            rb0 = *(const float4*)(Bbase + (size_t)brow * CC + kc + bkq);
        }
        #pragma unroll
        for (int k = 0; k < 16; k++) {
            float4 aLo = *(const float4*)&As[cur][k][rowgrp * 8];
            float4 aHi = *(const float4*)&As[cur][k][rowgrp * 8 + 4];
            float4 bb  = *(const float4*)&Bsh[cur][k][colgrp * 4];
            float a[8] = {aLo.x, aLo.y, aLo.z, aLo.w, aHi.x, aHi.y, aHi.z, aHi.w};
            float bv[4] = {bb.x, bb.y, bb.z, bb.w};
            #pragma unroll
            for (int i = 0; i < 8; i++)
                #pragma unroll
                for (int j = 0; j < 4; j++)
                    acc[i][j] = fmaf(a[i], bv[j], acc[i][j]);
        }
        if (more) {
            const int nxt = cur ^ 1;
            As[nxt][kbase + 0][arow] = ra0.x; As[nxt][kbase + 1][arow] = ra0.y;
            As[nxt][kbase + 2][arow] = ra0.z; As[nxt][kbase + 3][arow] = ra0.w;
            As[nxt][kbase + 4][arow] = ra1.x; As[nxt][kbase + 5][arow] = ra1.y;
            As[nxt][kbase + 6][arow] = ra1.z; As[nxt][kbase + 7][arow] = ra1.w;
            Bsh[nxt][bkq + 0][brow] = rb0.x; Bsh[nxt][bkq + 1][brow] = rb0.y;
            Bsh[nxt][bkq + 2][brow] = rb0.z; Bsh[nxt][bkq + 3][brow] = rb0.w;
            __syncthreads();
            cur = nxt;
        }
    }

    // bias + elu(.)+1
    float bvv[4];
    #pragma unroll
    for (int j = 0; j < 4; j++) bvv[j] = bias[c0 + colgrp * 4 + j];
    float v[8][4];
    #pragma unroll
    for (int i = 0; i < 8; i++)
        #pragma unroll
        for (int j = 0; j < 4; j++) {
            float pre = acc[i][j] + bvv[j];
            v[i][j] = (pre > 0.f) ? (pre + 1.f) : expf(pre);
        }

    if (mode == 0) {
        // ---- K mode: kk (row sums) + ksum partial (col sums) ----
        #pragma unroll
        for (int i = 0; i < 8; i++)
            red[rowgrp * 8 + i][colgrp] = v[i][0] + v[i][1] + v[i][2] + v[i][3];
        __syncthreads();
        if (tid < 128) {
            float s = 0.f;
            #pragma unroll
            for (int g = 0; g < 16; g++) s += red[tid][g];
            g_kk[(size_t)h * TT + t0 + tid] = s;
        }
        float cs[4];
        #pragma unroll
        for (int j = 0; j < 4; j++) {
            float s = 0.f;
            #pragma unroll
            for (int i = 0; i < 8; i++) s += v[i][j];
            cs[j] = s;
        }
        #pragma unroll
        for (int j = 0; j < 4; j++)
            cred[colgrp * 4 + j][rowgrp] = cs[j];
        __syncthreads();
        if (tid < 64) {
            float s = 0.f;
            #pragma unroll
            for (int g = 0; g < 16; g++) s += cred[tid][g];
            g_kpart[((size_t)h * 8 + tile8) * DD + tid] = s;
        }
    } else {
        // ---- Q mode: z = 1 / (q . ksum + eps) ----
        float4 ksv = *(const float4*)&g_ksum[(size_t)h * DD + colgrp * 4];
        float ks[4] = {ksv.x, ksv.y, ksv.z, ksv.w};
        #pragma unroll
        for (int i = 0; i < 8; i++) {
            float zp = v[i][0] * ks[0] + v[i][1] * ks[1] + v[i][2] * ks[2] + v[i][3] * ks[3];
            red[rowgrp * 8 + i][colgrp] = zp;
        }
        __syncthreads();
        if (tid < 128) {
            float s = 0.f;
            #pragma unroll
            for (int g = 0; g < 16; g++) s += red[tid][g];
            g_z[(size_t)h * TT + t0 + tid] = 1.f / (s + EPSV);
        }
    }
}

// ---- sum the 8 per-rowtile partials into ksum (deterministic, no atomics) ----
__global__ void reduce_ksum_kernel()
{
    int idx = blockIdx.x * blockDim.x + threadIdx.x;
    if (idx < NBM * NH * DD) {
        int hh = idx >> 6;
        int d  = idx & 63;
        float s = 0.f;
        #pragma unroll
        for (int p = 0; p < 8; p++)
            s += g_kpart[((size_t)hh * 8 + p) * DD + d];
        g_ksum[idx] = s;
    }
}

// ---- u[bm,n,c] = sum_t kk[bm,n,t] * x[bm,t,c]  (single x pass) ----
__global__ __launch_bounds__(128) void u_kernel(const float* __restrict__ x)
{
    __shared__ float skk[NH][TT];
    const int bm = blockIdx.y;
    const int c0 = blockIdx.x * 128;
    const int tid = threadIdx.x;
    for (int idx = tid; idx < NH * TT; idx += 128)
        skk[idx >> 10][idx & 1023] = g_kk[(size_t)bm * NH * TT + idx];
    __syncthreads();

    float acc[NH];
    #pragma unroll
    for (int nn = 0; nn < NH; nn++) acc[nn] = 0.f;
    const float* xp = x + (size_t)bm * TT * CC + c0 + tid;
    for (int t = 0; t < TT; t += 2) {
        float x0 = xp[(size_t)t * CC];
        float x1 = xp[(size_t)(t + 1) * CC];
        #pragma unroll
        for (int nn = 0; nn < NH; nn++) {
            float2 kp = *(const float2*)&skk[nn][t];
            acc[nn] = fmaf(kp.x, x0, fmaf(kp.y, x1, acc[nn]));
        }
    }
    #pragma unroll
    for (int nn = 0; nn < NH; nn++)
        g_u[((size_t)bm * NH + nn) * CC + c0 + tid] = acc[nn];
}

// ---- s[n,e] = u[n,:].wv_row + bv*Kt ;  ws[n,j] = sum_e s[n,e]*wp[j,nD+e] ----
__global__ __launch_bounds__(256) void sws_kernel(
    const float* __restrict__ wv, const float* __restrict__ bv,
    const float* __restrict__ wp)
{
    __shared__ float ss[CC];
    __shared__ float sKt[NH];
    const int bm = blockIdx.x;
    const int tid = threadIdx.x;
    if (tid < NH) {
        float s = 0.f;
        #pragma unroll
        for (int d = 0; d < DD; d++)
            s += g_ksum[((size_t)bm * NH + tid) * DD + d];
        sKt[tid] = s;
    }
    __syncthreads();
    for (int idx = tid; idx < CC; idx += 256) {
        int nn = idx >> 6;
        const float* up = g_u + ((size_t)bm * NH + nn) * CC;
        const float* wr = wv + (size_t)idx * CC;
        float dot = 0.f;
        for (int i = 0; i < CC; i += 4) {
            float4 uu = *(const float4*)(up + i);
            float4 ww = *(const float4*)(wr + i);
            dot += uu.x * ww.x + uu.y * ww.y + uu.z * ww.z + uu.w * ww.w;
        }
        ss[idx] = dot + bv[idx] * sKt[nn];
    }
    __syncthreads();
    for (int idx = tid; idx < NH * CC; idx += 256) {
        int nn = idx / CC;
        int jc = idx - nn * CC;
        const float* sp = ss + nn * DD;
        const float* wr = wp + (size_t)jc * CC + nn * DD;
        float dot = 0.f;
        #pragma unroll
        for (int e = 0; e < DD; e += 4) {
            float4 s4 = *(const float4*)(sp + e);
            float4 w4 = *(const float4*)(wr + e);
            dot += s4.x * w4.x + s4.y * w4.y + s4.z * w4.z + s4.w * w4.w;
        }
        g_ws[((size_t)bm * NH + nn) * CC + jc] = dot;
    }
}

// ---- out[bm,t,j] = sum_n z[n,t] * ws[n,j] + bp[j] ----
__global__ __launch_bounds__(256) void out_kernel(
    const float* __restrict__ bp, float* __restrict__ out)
{
    __shared__ float sws[NH][CC];
    __shared__ float sbp[CC];
    __shared__ float sz[NH][64];
    const int bm  = blockIdx.y;
    const int tr0 = blockIdx.x * 64;
    const int tid = threadIdx.x;
    for (int idx = tid; idx < NH * CC; idx += 256)
        sws[idx / CC][idx % CC] = g_ws[(size_t)bm * NH * CC + idx];
    for (int idx = tid; idx < CC; idx += 256) sbp[idx] = bp[idx];
    for (int idx = tid; idx < NH * 64; idx += 256)
        sz[idx >> 6][idx & 63] =
            g_z[((size_t)bm * NH + (idx >> 6)) * TT + tr0 + (idx & 63)];
    __syncthreads();

    for (int tt = 0; tt < 64; tt++) {
        float z[NH];
        #pragma unroll
        for (int nn = 0; nn < NH; nn++) z[nn] = sz[nn][tt];
        size_t ob = ((size_t)bm * TT + tr0 + tt) * CC;
        for (int cc = tid; cc < CC; cc += 256) {
            float a = sbp[cc];
            #pragma unroll
            for (int nn = 0; nn < NH; nn++)
                a = fmaf(z[nn], sws[nn][cc], a);
            out[ob + cc] = a;
        }
    }
}

extern "C" void kernel_launch(void* const* d_in, const int* in_sizes, int n_in,
                              void* d_out, int out_size)
{
    const float* x  = (const float*)d_in[0];
    const float* wq = (const float*)d_in[1];
    const float* bq = (const float*)d_in[2];
    const float* wk = (const float*)d_in[3];
    const float* bk = (const float*)d_in[4];
    const float* wv = (const float*)d_in[5];
    const float* bv = (const float*)d_in[6];
    const float* wp = (const float*)d_in[7];
    const float* bp = (const float*)d_in[8];
    float* out = (float*)d_out;

    dim3 pg(NH, 512);
    proj_kernel<<<pg, 256>>>(x, wk, bk, 0);                 // K proj + kk/ksum partials
    reduce_ksum_kernel<<<(NBM * NH * DD + 255) / 256, 256>>>();
    u_kernel<<<dim3(6, NBM), 128>>>(x);                     // u = kk-weighted x sums
    sws_kernel<<<NBM, 256>>>(wv, bv, wp);                   // s and ws (tiny GEMMs)
    proj_kernel<<<pg, 256>>>(x, wq, bq, 1);                 // Q proj -> z directly
    out_kernel<<<dim3(16, NBM), 256>>>(bp, out);            // rank-12 output update
}

// round 6
// speedup vs baseline: 2.0862x; 2.0848x over previous
#include <cuda_runtime.h>
#include <cuda_bf16.h>
#include <math.h>
#include <stdint.h>

#define NBM 64
#define TT 1024
#define CC 768
#define NH 12
#define DD 64
#define EPSV 1e-6f
#define RTOT 65536

// ---- scratch (device globals; allocation-free contract) ----
__device__ __align__(1024) __nv_bfloat16 g_xhi[RTOT * CC];
__device__ __align__(1024) __nv_bfloat16 g_xlo[RTOT * CC];
__device__ __align__(1024) __nv_bfloat16 g_whi[2][CC * CC];   // [0]=wk, [1]=wq
__device__ __align__(1024) __nv_bfloat16 g_wlo[2][CC * CC];
__device__ float g_kk  [NBM * NH * TT];
__device__ float g_kpart[NBM * NH * 8 * DD];
__device__ float g_ksum[NBM * NH * DD];
__device__ float g_u   [NBM * NH * CC];
__device__ float g_z   [NBM * NH * TT];
__device__ float g_s   [NBM * CC];
__device__ float g_ws  [NBM * NH * CC];

// ---------------- PTX helpers (base-target only: sm_80+ features) ----------------
__device__ __forceinline__ uint32_t smem_u32(const void* p) {
    uint32_t a;
    asm("{ .reg .u64 t; cvta.to.shared.u64 t, %1; cvt.u32.u64 %0, t; }" : "=r"(a) : "l"(p));
    return a;
}
__device__ __forceinline__ void cp16(uint32_t dst, const void* src) {
    asm volatile("cp.async.cg.shared.global [%0], [%1], 16;" :: "r"(dst), "l"(src));
}
__device__ __forceinline__ void cp_commit() {
    asm volatile("cp.async.commit_group;" ::: "memory");
}
__device__ __forceinline__ void cp_wait0() {
    asm volatile("cp.async.wait_group 0;" ::: "memory");
}
__device__ __forceinline__ void cp_wait1() {
    asm volatile("cp.async.wait_group 1;" ::: "memory");
}
__device__ __forceinline__ void ldm4(uint32_t* r, uint32_t addr) {
    asm volatile("ldmatrix.sync.aligned.m8n8.x4.shared.b16 {%0,%1,%2,%3}, [%4];"
        : "=r"(r[0]), "=r"(r[1]), "=r"(r[2]), "=r"(r[3]) : "r"(addr));
}
__device__ __forceinline__ void mma16816(float* c, const uint32_t* a, const uint32_t* b) {
    asm volatile(
        "mma.sync.aligned.m16n8k16.row.col.f32.bf16.bf16.f32 "
        "{%0,%1,%2,%3}, {%4,%5,%6,%7}, {%8,%9}, {%0,%1,%2,%3};"
        : "+f"(c[0]), "+f"(c[1]), "+f"(c[2]), "+f"(c[3])
        : "r"(a[0]), "r"(a[1]), "r"(a[2]), "r"(a[3]), "r"(b[0]), "r"(b[1]));
}

// ---------------- fp32 -> bf16 hi/lo split ----------------
__global__ __launch_bounds__(256) void conv_split(
    const float4* __restrict__ in, __nv_bfloat162* __restrict__ hi,
    __nv_bfloat162* __restrict__ lo, int n4)
{
    int i = blockIdx.x * blockDim.x + threadIdx.x;
    if (i >= n4) return;
    float4 v = in[i];
    __nv_bfloat16 h0 = __float2bfloat16(v.x), h1 = __float2bfloat16(v.y);
    __nv_bfloat16 h2 = __float2bfloat16(v.z), h3 = __float2bfloat16(v.w);
    hi[2 * i]     = __nv_bfloat162(h0, h1);
    hi[2 * i + 1] = __nv_bfloat162(h2, h3);
    lo[2 * i]     = __nv_bfloat162(__float2bfloat16(v.x - __bfloat162float(h0)),
                                   __float2bfloat16(v.y - __bfloat162float(h1)));
    lo[2 * i + 1] = __nv_bfloat162(__float2bfloat16(v.z - __bfloat162float(h2)),
                                   __float2bfloat16(v.w - __bfloat162float(h3)));
}

// ---------------- warp-MMA projection GEMM ----------------
// CTA: 128 rows x 256 cols (4 heads) x K-step 32, 8 warps (2x4 of 64x64),
// split-precision bf16 (3 mma passes), double-buffered cp.async.
// mode 0 (K): epilogue -> g_kk, g_kpart.  mode 1 (Q): epilogue -> g_z.
#define BK 32
#define STRIDE_B 80                  // 40 bf16 per row (32 + 8 pad)
#define A_HI_OFF 0
#define A_LO_OFF 10240
#define B_HI_OFF 20480
#define B_LO_OFF 40960
#define STAGE_BYTES 61440
#define PROJ_SMEM (2 * STAGE_BYTES)

__device__ __forceinline__ void load_stage(
    uint32_t st, const __nv_bfloat16* ah, const __nv_bfloat16* al,
    const __nv_bfloat16* bh, const __nv_bfloat16* bl,
    int r0, int c0, int k0, int tid)
{
    #pragma unroll
    for (int q = 0; q < 2; q++) {
        int u = q * 256 + tid;
        int row = u >> 2, ch = u & 3;
        size_t g = (size_t)(r0 + row) * CC + k0 + ch * 8;
        uint32_t d = st + row * STRIDE_B + ch * 16;
        cp16(d + A_HI_OFF, ah + g);
        cp16(d + A_LO_OFF, al + g);
    }
    #pragma unroll
    for (int q = 0; q < 4; q++) {
        int u = q * 256 + tid;
        int row = u >> 2, ch = u & 3;
        size_t g = (size_t)(c0 + row) * CC + k0 + ch * 8;
        uint32_t d = st + row * STRIDE_B + ch * 16;
        cp16(d + B_HI_OFF, bh + g);
        cp16(d + B_LO_OFF, bl + g);
    }
}

__global__ __launch_bounds__(256, 1) void proj_mma(
    const __nv_bfloat16* __restrict__ ah, const __nv_bfloat16* __restrict__ al,
    const __nv_bfloat16* __restrict__ bh, const __nv_bfloat16* __restrict__ bl,
    const float* __restrict__ bias, int mode)
{
    extern __shared__ char sm[];
    __shared__ float sbias[256];
    __shared__ float sks[256];
    __shared__ float cred[2][4][64];

    const int tid = threadIdx.x;
    const int wid = tid >> 5, lane = tid & 31;
    const int warp_m = wid >> 2, warp_n = wid & 3;
    const int ct = blockIdx.x;               // 0..2  (4 heads each)
    const int ry = blockIdx.y;               // 0..511
    const int r0 = ry << 7, c0 = ct << 8;
    const int bm = ry >> 3, tl = ry & 7;
    const uint32_t sb = smem_u32(sm);

    sbias[tid] = bias[c0 + tid];
    if (mode == 1)
        sks[tid] = g_ksum[((size_t)bm * NH + ct * 4 + (tid >> 6)) * DD + (tid & 63)];

    float acc[4][8][4];
    #pragma unroll
    for (int mi = 0; mi < 4; mi++)
        #pragma unroll
        for (int ni = 0; ni < 8; ni++)
            #pragma unroll
            for (int r = 0; r < 4; r++) acc[mi][ni][r] = 0.f;

    // ldmatrix per-lane address offsets
    const uint32_t aoff = (uint32_t)((lane & 15) * STRIDE_B + ((lane >> 4) & 1) * 16);
    const uint32_t boff = (uint32_t)(((lane & 7) + ((lane >> 4) & 1) * 8) * STRIDE_B
                                     + ((lane >> 3) & 1) * 16);

    load_stage(sb, ah, al, bh, bl, r0, c0, 0, tid);
    cp_commit();

    for (int ks = 0; ks < 24; ks++) {
        const uint32_t st = sb + (uint32_t)(ks & 1) * STAGE_BYTES;
        if (ks + 1 < 24) {
            load_stage(sb + (uint32_t)((ks + 1) & 1) * STAGE_BYTES,
                       ah, al, bh, bl, r0, c0, (ks + 1) * BK, tid);
            cp_commit();
            cp_wait1();
        } else {
            cp_wait0();
        }
        __syncthreads();

        #pragma unroll
        for (int kk = 0; kk < 2; kk++) {
            const uint32_t kb = (uint32_t)(kk * 32);   // k16 * 2 bytes
            uint32_t afh[4][4], afl[4][4], bfh[4][4], bfl[4][4];
            #pragma unroll
            for (int mi = 0; mi < 4; mi++)
                ldm4(afh[mi], st + A_HI_OFF + (uint32_t)((warp_m * 64 + mi * 16) * STRIDE_B) + kb + aoff);
            #pragma unroll
            for (int ng = 0; ng < 4; ng++)
                ldm4(bfh[ng], st + B_HI_OFF + (uint32_t)((warp_n * 64 + ng * 16) * STRIDE_B) + kb + boff);
            #pragma unroll
            for (int mi = 0; mi < 4; mi++)
                #pragma unroll
                for (int ng = 0; ng < 4; ng++) {
                    mma16816(acc[mi][2 * ng],     afh[mi], &bfh[ng][0]);
                    mma16816(acc[mi][2 * ng + 1], afh[mi], &bfh[ng][2]);
                }
            #pragma unroll
            for (int ng = 0; ng < 4; ng++)
                ldm4(bfl[ng], st + B_LO_OFF + (uint32_t)((warp_n * 64 + ng * 16) * STRIDE_B) + kb + boff);
            #pragma unroll
            for (int mi = 0; mi < 4; mi++)
                #pragma unroll
                for (int ng = 0; ng < 4; ng++) {
                    mma16816(acc[mi][2 * ng],     afh[mi], &bfl[ng][0]);
                    mma16816(acc[mi][2 * ng + 1], afh[mi], &bfl[ng][2]);
                }
            #pragma unroll
            for (int mi = 0; mi < 4; mi++)
                ldm4(afl[mi], st + A_LO_OFF + (uint32_t)((warp_m * 64 + mi * 16) * STRIDE_B) + kb + aoff);
            #pragma unroll
            for (int mi = 0; mi < 4; mi++)
                #pragma unroll
                for (int ng = 0; ng < 4; ng++) {
                    mma16816(acc[mi][2 * ng],     afl[mi], &bfh[ng][0]);
                    mma16816(acc[mi][2 * ng + 1], afl[mi], &bfh[ng][2]);
                }
        }
        __syncthreads();
    }

    // ---------------- fused epilogue ----------------
    // C frag: regs 0,1 -> row lane/4, cols 2*(lane&3)+{0,1}; regs 2,3 -> row lane/4+8
    const int hg = ct * 4 + warp_n;                  // global head
    const int cb = warp_n * 64 + 2 * (lane & 3);     // col base in CTA
    float colacc[8][2];
    #pragma unroll
    for (int ni = 0; ni < 8; ni++) { colacc[ni][0] = 0.f; colacc[ni][1] = 0.f; }

    #pragma unroll
    for (int mi = 0; mi < 4; mi++) {
        float rs0 = 0.f, rs1 = 0.f;
        #pragma unroll
        for (int ni = 0; ni < 8; ni++) {
            const float b0 = sbias[cb + ni * 8], b1 = sbias[cb + ni * 8 + 1];
            #pragma unroll
            for (int r = 0; r < 4; r++) {
                float pre = acc[mi][ni][r] + ((r & 1) ? b1 : b0);
                float v = (pre > 0.f) ? (pre + 1.f) : __expf(pre);
                if (mode == 0) {
                    if (r < 2) rs0 += v; else rs1 += v;
                    colacc[ni][r & 1] += v;
                } else {
                    float w = sks[cb + ni * 8 + (r & 1)];
                    if (r < 2) rs0 += v * w; else rs1 += v * w;
                }
            }
        }
        rs0 += __shfl_xor_sync(0xffffffffu, rs0, 1);
        rs0 += __shfl_xor_sync(0xffffffffu, rs0, 2);
        rs1 += __shfl_xor_sync(0xffffffffu, rs1, 1);
        rs1 += __shfl_xor_sync(0xffffffffu, rs1, 2);
        if ((lane & 3) == 0) {
            int rowa = tl * 128 + warp_m * 64 + mi * 16 + (lane >> 2);
            size_t base = ((size_t)bm * NH + hg) * TT;
            if (mode == 0) {
                g_kk[base + rowa]     = rs0;
                g_kk[base + rowa + 8] = rs1;
            } else {
                g_z[base + rowa]     = 1.f / (rs0 + EPSV);
                g_z[base + rowa + 8] = 1.f / (rs1 + EPSV);
            }
        }
    }

    if (mode == 0) {
        #pragma unroll
        for (int ni = 0; ni < 8; ni++)
            #pragma unroll
            for (int j = 0; j < 2; j++) {
                float c = colacc[ni][j];
                c += __shfl_xor_sync(0xffffffffu, c, 4);
                c += __shfl_xor_sync(0xffffffffu, c, 8);
                c += __shfl_xor_sync(0xffffffffu, c, 16);
                if (lane < 4 && (int)(lane) == (int)(lane & 3)) {
                    // lane 0..3 holds totals for col pair of its (lane&3)
                    cred[warp_m][warp_n][ni * 8 + 2 * lane + j] = c;
                }
            }
        __syncthreads();
        int head = tid >> 6, d = tid & 63;
        float s = cred[0][head][d] + cred[1][head][d];
        g_kpart[(((size_t)bm * NH + ct * 4 + head) * 8 + tl) * DD + d] = s;
    }
}

// ---------------- ksum reduce ----------------
__global__ void reduce_ksum_kernel()
{
    int idx = blockIdx.x * blockDim.x + threadIdx.x;
    if (idx < NBM * NH * DD) {
        int hh = idx >> 6, d = idx & 63;
        float s = 0.f;
        #pragma unroll
        for (int p = 0; p < 8; p++)
            s += g_kpart[((size_t)hh * 8 + p) * DD + d];
        g_ksum[idx] = s;
    }
}

// ---------------- u[bm,n,c] = sum_t kk[bm,n,t] * x[bm,t,c] ----------------
__global__ __launch_bounds__(128) void u_kernel(const float* __restrict__ x)
{
    __shared__ float skk[NH][TT];
    const int bm = blockIdx.y, c0 = blockIdx.x * 128, tid = threadIdx.x;
    for (int idx = tid; idx < NH * TT; idx += 128)
        skk[idx >> 10][idx & 1023] = g_kk[(size_t)bm * NH * TT + idx];
    __syncthreads();
    float acc[NH];
    #pragma unroll
    for (int nn = 0; nn < NH; nn++) acc[nn] = 0.f;
    const float* xp = x + (size_t)bm * TT * CC + c0 + tid;
    for (int t = 0; t < TT; t += 2) {
        float x0 = xp[(size_t)t * CC];
        float x1 = xp[(size_t)(t + 1) * CC];
        #pragma unroll
        for (int nn = 0; nn < NH; nn++) {
            float2 kp = *(const float2*)&skk[nn][t];
            acc[nn] = fmaf(kp.x, x0, fmaf(kp.y, x1, acc[nn]));
        }
    }
    #pragma unroll
    for (int nn = 0; nn < NH; nn++)
        g_u[((size_t)bm * NH + nn) * CC + c0 + tid] = acc[nn];
}

// ---- s[bm, n*64+c] = u[bm,n,:].wv[n*64+c,:] + bv[n*64+c]*Kt[bm,n] ----
__global__ __launch_bounds__(256) void s_kernel(
    const float* __restrict__ wv, const float* __restrict__ bv)
{
    __shared__ __align__(16) float swv[64][68];
    __shared__ __align__(16) float su[64][68];
    __shared__ float sKt[64];
    const int n = blockIdx.x, tid = threadIdx.x;
    if (tid < 64) {
        float s = 0.f;
        #pragma unroll
        for (int d = 0; d < DD; d++)
            s += g_ksum[((size_t)tid * NH + n) * DD + d];
        sKt[tid] = s;
    }
    float acc[4][4];
    #pragma unroll
    for (int i = 0; i < 4; i++)
        #pragma unroll
        for (int j = 0; j < 4; j++) acc[i][j] = 0.f;
    const int cg = tid & 15, bg = tid >> 4;
    const int lrow = tid & 63, kq = tid >> 6;

    for (int kc = 0; kc < 12; kc++) {
        __syncthreads();
        const float* wr = wv + (size_t)(n * 64 + lrow) * CC + kc * 64 + kq * 16;
        const float* ur = g_u + ((size_t)lrow * NH + n) * CC + kc * 64 + kq * 16;
        #pragma unroll
        for (int i = 0; i < 4; i++) {
            float4 w4 = *(const float4*)(wr + i * 4);
            float4 u4 = *(const float4*)(ur + i * 4);
            int k = kq * 16 + i * 4;
            swv[k + 0][lrow] = w4.x; swv[k + 1][lrow] = w4.y;
            swv[k + 2][lrow] = w4.z; swv[k + 3][lrow] = w4.w;
            su[k + 0][lrow] = u4.x; su[k + 1][lrow] = u4.y;
            su[k + 2][lrow] = u4.z; su[k + 3][lrow] = u4.w;
        }
        __syncthreads();
        #pragma unroll 4
        for (int k = 0; k < 64; k++) {
            float4 a4 = *(const float4*)&su[k][bg * 4];
            float4 b4 = *(const float4*)&swv[k][cg * 4];
            float a[4] = {a4.x, a4.y, a4.z, a4.w};
            float b[4] = {b4.x, b4.y, b4.z, b4.w};
            #pragma unroll
            for (int i = 0; i < 4; i++)
                #pragma unroll
                for (int j = 0; j < 4; j++)
                    acc[i][j] = fmaf(a[i], b[j], acc[i][j]);
        }
    }
    #pragma unroll
    for (int i = 0; i < 4; i++)
        #pragma unroll
        for (int j = 0; j < 4; j++) {
            int bmv = bg * 4 + i, c = cg * 4 + j;
            g_s[(size_t)bmv * CC + n * 64 + c] = acc[i][j] + bv[n * 64 + c] * sKt[bmv];
        }
}

// ---- ws[bm,n,j] = s[bm,n*64:].wp[j,n*64:] ; grid (12 jtiles x NH) ----
__global__ __launch_bounds__(256) void ws_kernel(const float* __restrict__ wp)
{
    __shared__ __align__(16) float wpp[64][68];
    __shared__ __align__(16) float ssm[64][68];
    const int j0 = blockIdx.x * 64, n = blockIdx.y, tid = threadIdx.x;
    for (int q = 0; q < 4; q++) {
        int u = q * 256 + tid;
        int r = u >> 4, e4 = u & 15;
        float4 v = *(const float4*)(wp + (size_t)(j0 + r) * CC + n * 64 + e4 * 4);
        wpp[e4 * 4 + 0][r] = v.x; wpp[e4 * 4 + 1][r] = v.y;
        wpp[e4 * 4 + 2][r] = v.z; wpp[e4 * 4 + 3][r] = v.w;
    }
    for (int q = 0; q < 4; q++) {
        int u = q * 256 + tid;
        int b = u >> 4, e4 = u & 15;
        float4 v = *(const float4*)(g_s + (size_t)b * CC + n * 64 + e4 * 4);
        ssm[e4 * 4 + 0][b] = v.x; ssm[e4 * 4 + 1][b] = v.y;
        ssm[e4 * 4 + 2][b] = v.z; ssm[e4 * 4 + 3][b] = v.w;
    }
    __syncthreads();
    const int tx = tid & 31, ty = tid >> 5;
    float acc[8][2];
    #pragma unroll
    for (int i = 0; i < 8; i++) { acc[i][0] = 0.f; acc[i][1] = 0.f; }
    #pragma unroll 4
    for (int e = 0; e < 64; e++) {
        float4 a0 = *(const float4*)&ssm[e][ty * 8];
        float4 a1 = *(const float4*)&ssm[e][ty * 8 + 4];
        float2 b2 = *(const float2*)&wpp[e][tx * 2];
        float a[8] = {a0.x, a0.y, a0.z, a0.w, a1.x, a1.y, a1.z, a1.w};
        #pragma unroll
        for (int i = 0; i < 8; i++) {
            acc[i][0] = fmaf(a[i], b2.x, acc[i][0]);
            acc[i][1] = fmaf(a[i], b2.y, acc[i][1]);
        }
    }
    #pragma unroll
    for (int i = 0; i < 8; i++) {
        int bmv = ty * 8 + i;
        g_ws[((size_t)bmv * NH + n) * CC + j0 + tx * 2 + 0] = acc[i][0];
        g_ws[((size_t)bmv * NH + n) * CC + j0 + tx * 2 + 1] = acc[i][1];
    }
}

// ---- out[bm,t,j] = sum_n z[n,t]*ws[n,j] + bp[j] ----
__global__ __launch_bounds__(256) void out_kernel(
    const float* __restrict__ bp, float* __restrict__ out)
{
    __shared__ __align__(16) float sws[NH][CC];
    __shared__ __align__(16) float sbp[CC];
    __shared__ float sz[NH][128];
    const int bm = blockIdx.y, t0 = blockIdx.x * 128, tid = threadIdx.x;
    for (int idx = tid; idx < NH * CC; idx += 256)
        sws[idx / CC][idx % CC] = g_ws[(size_t)bm * NH * CC + idx];
    for (int idx = tid; idx < CC; idx += 256) sbp[idx] = bp[idx];
    for (int idx = tid; idx < NH * 128; idx += 256)
        sz[idx >> 7][idx & 127] =
            g_z[((size_t)bm * NH + (idx >> 7)) * TT + t0 + (idx & 127)];
    __syncthreads();

    const int r = tid >> 1, half = tid & 1;
    float z[NH];
    #pragma unroll
    for (int n = 0; n < NH; n++) z[n] = sz[n][r];
    float4* out4 = (float4*)(out + ((size_t)bm * TT + t0 + r) * CC);
    const float4* bp4 = (const float4*)sbp;
    for (int k = 0; k < 96; k++) {
        int c4 = half * 96 + k;
        float4 a = bp4[c4];
        #pragma unroll
        for (int n = 0; n < NH; n++) {
            float4 w = *(const float4*)&sws[n][c4 * 4];
            a.x = fmaf(z[n], w.x, a.x);
            a.y = fmaf(z[n], w.y, a.y);
            a.z = fmaf(z[n], w.z, a.z);
            a.w = fmaf(z[n], w.w, a.w);
        }
        out4[c4] = a;
    }
}

// ---------------- host ----------------
extern "C" void kernel_launch(void* const* d_in, const int* in_sizes, int n_in,
                              void* d_out, int out_size)
{
    const float* x  = (const float*)d_in[0];
    const float* wq = (const float*)d_in[1];
    const float* bq = (const float*)d_in[2];
    const float* wk = (const float*)d_in[3];
    const float* bk = (const float*)d_in[4];
    const float* wv = (const float*)d_in[5];
    const float* bv = (const float*)d_in[6];
    const float* wp = (const float*)d_in[7];
    const float* bp = (const float*)d_in[8];
    float* out = (float*)d_out;

    cudaFuncSetAttribute(proj_mma, cudaFuncAttributeMaxDynamicSharedMemorySize, PROJ_SMEM);

    __nv_bfloat16 *xhi, *xlo, *wkh, *wkl, *wqh, *wql;
    cudaGetSymbolAddress((void**)&xhi, g_xhi);
    cudaGetSymbolAddress((void**)&xlo, g_xlo);
    cudaGetSymbolAddress((void**)&wkh, g_whi);
    cudaGetSymbolAddress((void**)&wkl, g_wlo);
    wqh = wkh + CC * CC;
    wql = wkl + CC * CC;

    const int n4x = RTOT * CC / 4;
    const int n4w = CC * CC / 4;
    conv_split<<<(n4x + 255) / 256, 256>>>((const float4*)x,
        (__nv_bfloat162*)xhi, (__nv_bfloat162*)xlo, n4x);
    conv_split<<<(n4w + 255) / 256, 256>>>((const float4*)wk,
        (__nv_bfloat162*)wkh, (__nv_bfloat162*)wkl, n4w);
    conv_split<<<(n4w + 255) / 256, 256>>>((const float4*)wq,
        (__nv_bfloat162*)wqh, (__nv_bfloat162*)wql, n4w);

    dim3 pg(3, 512);
    proj_mma<<<pg, 256, PROJ_SMEM>>>(xhi, xlo, wkh, wkl, bk, 0);   // K -> kk, kpart
    reduce_ksum_kernel<<<(NBM * NH * DD + 255) / 256, 256>>>();
    u_kernel<<<dim3(6, NBM), 128>>>(x);
    s_kernel<<<NH, 256>>>(wv, bv);
    ws_kernel<<<dim3(12, NH), 256>>>(wp);
    proj_mma<<<pg, 256, PROJ_SMEM>>>(xhi, xlo, wqh, wql, bq, 1);   // Q -> z
    out_kernel<<<dim3(8, NBM), 256>>>(bp, out);
}

// round 8
// speedup vs baseline: 3.4896x; 1.6727x over previous
#include <cuda_runtime.h>
#include <cuda_fp16.h>
#include <math.h>
#include <stdint.h>

#define NBM 64
#define TT 1024
#define CC 768
#define NH 12
#define DD 64
#define EPSV 1e-6f
#define RTOT 65536

// ---- scratch (device globals; allocation-free contract) ----
__device__ __align__(1024) __half g_xh[RTOT * CC];
__device__ __align__(1024) __half g_wh[2][CC * CC];   // [0]=wk, [1]=wq
__device__ float g_kk  [NBM * NH * TT];
__device__ float g_kpart[NBM * NH * 8 * DD];
__device__ float g_ksum[NBM * NH * DD];
__device__ float g_u   [NBM * NH * CC];
__device__ float g_z   [NBM * NH * TT];
__device__ float g_s   [NBM * CC];
__device__ float g_ws  [NBM * NH * CC];

// ---------------- PTX helpers (base-target sm_80+) ----------------
__device__ __forceinline__ uint32_t smem_u32(const void* p) {
    uint32_t a;
    asm("{ .reg .u64 t; cvta.to.shared.u64 t, %1; cvt.u32.u64 %0, t; }" : "=r"(a) : "l"(p));
    return a;
}
__device__ __forceinline__ void cp16(uint32_t dst, const void* src) {
    asm volatile("cp.async.cg.shared.global [%0], [%1], 16;" :: "r"(dst), "l"(src));
}
__device__ __forceinline__ void cp_commit() {
    asm volatile("cp.async.commit_group;" ::: "memory");
}
__device__ __forceinline__ void cp_wait0() { asm volatile("cp.async.wait_group 0;" ::: "memory"); }
__device__ __forceinline__ void cp_wait1() { asm volatile("cp.async.wait_group 1;" ::: "memory"); }
__device__ __forceinline__ void cp_wait2() { asm volatile("cp.async.wait_group 2;" ::: "memory"); }
__device__ __forceinline__ void ldm4(uint32_t* r, uint32_t addr) {
    asm volatile("ldmatrix.sync.aligned.m8n8.x4.shared.b16 {%0,%1,%2,%3}, [%4];"
        : "=r"(r[0]), "=r"(r[1]), "=r"(r[2]), "=r"(r[3]) : "r"(addr));
}
__device__ __forceinline__ void mma16816(float* c, const uint32_t* a, const uint32_t* b) {
    asm volatile(
        "mma.sync.aligned.m16n8k16.row.col.f32.f16.f16.f32 "
        "{%0,%1,%2,%3}, {%4,%5,%6,%7}, {%8,%9}, {%0,%1,%2,%3};"
        : "+f"(c[0]), "+f"(c[1]), "+f"(c[2]), "+f"(c[3])
        : "r"(a[0]), "r"(a[1]), "r"(a[2]), "r"(a[3]), "r"(b[0]), "r"(b[1]));
}

// ---------------- fp32 -> fp16 ----------------
__global__ __launch_bounds__(256) void conv_h(
    const float4* __restrict__ in, __half2* __restrict__ out, int n4)
{
    int i = blockIdx.x * blockDim.x + threadIdx.x;
    if (i >= n4) return;
    float4 v = in[i];
    out[2 * i]     = __floats2half2_rn(v.x, v.y);
    out[2 * i + 1] = __floats2half2_rn(v.z, v.w);
}

// ---------------- warp-MMA projection GEMM (single-pass fp16) ----------------
// CTA: 128 rows x 256 cols (4 heads), 16 warps (2x8) of 64x32 warp tiles,
// K-step 32, 3-stage cp.async ring.
// mode 0 (K): epilogue -> g_kk, g_kpart.  mode 1 (Q): epilogue -> g_z.
#define BK 32
#define STRIDE_B 80                   // 32 halfs (64B) + 16B pad
#define A_OFF 0
#define B_OFF 10240
#define STAGE_BYTES 30720
#define NSTAGE 3
#define PROJ_SMEM (NSTAGE * STAGE_BYTES)

__device__ __forceinline__ void load_stage(
    uint32_t st, const __half* a, const __half* b,
    int r0, int c0, int k0, int tid)
{
    {
        int row = tid >> 2, ch = tid & 3;
        cp16(st + A_OFF + row * STRIDE_B + ch * 16,
             a + (size_t)(r0 + row) * CC + k0 + ch * 8);
    }
    #pragma unroll
    for (int q = 0; q < 2; q++) {
        int u = q * 512 + tid;
        int row = u >> 2, ch = u & 3;
        cp16(st + B_OFF + row * STRIDE_B + ch * 16,
             b + (size_t)(c0 + row) * CC + k0 + ch * 8);
    }
}

__global__ __launch_bounds__(512, 1) void proj_mma(
    const __half* __restrict__ a, const __half* __restrict__ bw,
    const float* __restrict__ bias, int mode)
{
    extern __shared__ char sm[];
    __shared__ float sbias[256];
    __shared__ float sks[256];
    __shared__ float rowred[8][128];
    __shared__ float colred[2][8][32];

    const int tid = threadIdx.x;
    const int wid = tid >> 5, lane = tid & 31;
    const int warp_m = wid >> 3;          // 0..1 (64 rows)
    const int warp_n = wid & 7;           // 0..7 (32 cols)
    const int ct = blockIdx.x;            // 0..2 (4 heads each)
    const int ry = blockIdx.y;            // 0..511
    const int r0 = ry << 7, c0 = ct << 8;
    const int bm = ry >> 3, tl = ry & 7;
    const uint32_t sb = smem_u32(sm);

    if (tid < 256) {
        sbias[tid] = bias[c0 + tid];
        if (mode == 1)
            sks[tid] = g_ksum[((size_t)bm * NH + ct * 4 + (tid >> 6)) * DD + (tid & 63)];
    }

    float acc[4][4][4];
    #pragma unroll
    for (int mi = 0; mi < 4; mi++)
        #pragma unroll
        for (int ni = 0; ni < 4; ni++)
            #pragma unroll
            for (int r = 0; r < 4; r++) acc[mi][ni][r] = 0.f;

    const uint32_t aoff = (uint32_t)((lane & 15) * STRIDE_B + (lane >> 4) * 16);
    const uint32_t boff = (uint32_t)(((lane & 7) + ((lane >> 4) & 1) * 8) * STRIDE_B
                                     + ((lane >> 3) & 1) * 16);

    load_stage(sb, a, bw, r0, c0, 0, tid);
    cp_commit();
    load_stage(sb + STAGE_BYTES, a, bw, r0, c0, BK, tid);
    cp_commit();

    for (int ks = 0; ks < 24; ks++) {
        if (ks + 2 < 24) {
            load_stage(sb + (uint32_t)(((ks + 2) % NSTAGE) * STAGE_BYTES),
                       a, bw, r0, c0, (ks + 2) * BK, tid);
            cp_commit();
            cp_wait2();
        } else if (ks + 1 < 24) {
            cp_wait1();
        } else {
            cp_wait0();
        }
        __syncthreads();

        const uint32_t st = sb + (uint32_t)((ks % NSTAGE) * STAGE_BYTES);
        #pragma unroll
        for (int kk = 0; kk < 2; kk++) {
            const uint32_t kb = (uint32_t)(kk * 32);
            uint32_t af[4][4], bf[2][4];
            #pragma unroll
            for (int mi = 0; mi < 4; mi++)
                ldm4(af[mi], st + A_OFF + (uint32_t)((warp_m * 64 + mi * 16) * STRIDE_B) + kb + aoff);
            #pragma unroll
            for (int ng = 0; ng < 2; ng++)
                ldm4(bf[ng], st + B_OFF + (uint32_t)((warp_n * 32 + ng * 16) * STRIDE_B) + kb + boff);
            #pragma unroll
            for (int mi = 0; mi < 4; mi++)
                #pragma unroll
                for (int ng = 0; ng < 2; ng++) {
                    mma16816(acc[mi][2 * ng],     af[mi], &bf[ng][0]);
                    mma16816(acc[mi][2 * ng + 1], af[mi], &bf[ng][2]);
                }
        }
        __syncthreads();
    }

    // ---------------- fused epilogue ----------------
    // C frag (m16n8): regs {0,1} -> row lane>>2, cols 2*(lane&3)+{0,1};
    //                 regs {2,3} -> row (lane>>2)+8.
    const int cb = warp_n * 32 + 2 * (lane & 3);
    float colacc[4][2];
    #pragma unroll
    for (int ni = 0; ni < 4; ni++) { colacc[ni][0] = 0.f; colacc[ni][1] = 0.f; }

    #pragma unroll
    for (int mi = 0; mi < 4; mi++) {
        float rs0 = 0.f, rs1 = 0.f;
        #pragma unroll
        for (int ni = 0; ni < 4; ni++) {
            const float b0 = sbias[cb + ni * 8], b1 = sbias[cb + ni * 8 + 1];
            #pragma unroll
            for (int r = 0; r < 4; r++) {
                float pre = acc[mi][ni][r] + ((r & 1) ? b1 : b0);
                float v = (pre > 0.f) ? (pre + 1.f) : __expf(pre);
                if (mode == 0) {
                    colacc[ni][r & 1] += v;
                    if (r < 2) rs0 += v; else rs1 += v;
                } else {
                    float w = sks[cb + ni * 8 + (r & 1)];
                    if (r < 2) rs0 += v * w; else rs1 += v * w;
                }
            }
        }
        rs0 += __shfl_xor_sync(0xffffffffu, rs0, 1);
        rs0 += __shfl_xor_sync(0xffffffffu, rs0, 2);
        rs1 += __shfl_xor_sync(0xffffffffu, rs1, 1);
        rs1 += __shfl_xor_sync(0xffffffffu, rs1, 2);
        if ((lane & 3) == 0) {
            int row = warp_m * 64 + mi * 16 + (lane >> 2);
            rowred[warp_n][row]     = rs0;
            rowred[warp_n][row + 8] = rs1;
        }
    }

    if (mode == 0) {
        #pragma unroll
        for (int ni = 0; ni < 4; ni++)
            #pragma unroll
            for (int j = 0; j < 2; j++) {
                float c = colacc[ni][j];
                c += __shfl_xor_sync(0xffffffffu, c, 4);
                c += __shfl_xor_sync(0xffffffffu, c, 8);
                c += __shfl_xor_sync(0xffffffffu, c, 16);
                if (lane < 4)
                    colred[warp_m][warp_n][ni * 8 + lane * 2 + j] = c;
            }
    }
    __syncthreads();

    if (mode == 0) {
        // kk: combine warp_n pairs (head = warp_n>>1)
        {
            int hh = tid >> 7, row = tid & 127;
            float v = rowred[2 * hh][row] + rowred[2 * hh + 1][row];
            g_kk[((size_t)bm * NH + ct * 4 + hh) * TT + tl * 128 + row] = v;
        }
        if (tid < 256) {
            int wn = tid >> 5, c = tid & 31;
            int col = wn * 32 + c;
            int hh = col >> 6, d = col & 63;
            float v = colred[0][wn][c] + colred[1][wn][c];
            g_kpart[(((size_t)bm * NH + ct * 4 + hh) * 8 + tl) * DD + d] = v;
        }
    } else {
        int hh = tid >> 7, row = tid & 127;
        float sum = rowred[2 * hh][row] + rowred[2 * hh + 1][row];
        g_z[((size_t)bm * NH + ct * 4 + hh) * TT + tl * 128 + row] = 1.f / (sum + EPSV);
    }
}

// ---------------- ksum reduce ----------------
__global__ void reduce_ksum_kernel()
{
    int idx = blockIdx.x * blockDim.x + threadIdx.x;
    if (idx < NBM * NH * DD) {
        int hh = idx >> 6, d = idx & 63;
        float s = 0.f;
        #pragma unroll
        for (int p = 0; p < 8; p++)
            s += g_kpart[((size_t)hh * 8 + p) * DD + d];
        g_ksum[idx] = s;
    }
}

// ---------------- u[bm,n,c] = sum_t kk[bm,n,t] * x[bm,t,c] ----------------
__global__ __launch_bounds__(128) void u_kernel(const float* __restrict__ x)
{
    __shared__ float skk[NH][TT];
    const int bm = blockIdx.y, c0 = blockIdx.x * 128, tid = threadIdx.x;
    for (int idx = tid; idx < NH * TT; idx += 128)
        skk[idx >> 10][idx & 1023] = g_kk[(size_t)bm * NH * TT + idx];
    __syncthreads();
    float acc[NH];
    #pragma unroll
    for (int nn = 0; nn < NH; nn++) acc[nn] = 0.f;
    const float* xp = x + (size_t)bm * TT * CC + c0 + tid;
    for (int t = 0; t < TT; t += 2) {
        float x0 = xp[(size_t)t * CC];
        float x1 = xp[(size_t)(t + 1) * CC];
        #pragma unroll
        for (int nn = 0; nn < NH; nn++) {
            float2 kp = *(const float2*)&skk[nn][t];
            acc[nn] = fmaf(kp.x, x0, fmaf(kp.y, x1, acc[nn]));
        }
    }
    #pragma unroll
    for (int nn = 0; nn < NH; nn++)
        g_u[((size_t)bm * NH + nn) * CC + c0 + tid] = acc[nn];
}

// ---- s[bm, n*64+c] = u[bm,n,:].wv[n*64+c,:] + bv[n*64+c]*Kt[bm,n] ----
__global__ __launch_bounds__(256) void s_kernel(
    const float* __restrict__ wv, const float* __restrict__ bv)
{
    __shared__ __align__(16) float swv[64][68];
    __shared__ __align__(16) float su[64][68];
    __shared__ float sKt[64];
    const int n = blockIdx.x, tid = threadIdx.x;
    if (tid < 64) {
        float s = 0.f;
        #pragma unroll
        for (int d = 0; d < DD; d++)
            s += g_ksum[((size_t)tid * NH + n) * DD + d];
        sKt[tid] = s;
    }
    float acc[4][4];
    #pragma unroll
    for (int i = 0; i < 4; i++)
        #pragma unroll
        for (int j = 0; j < 4; j++) acc[i][j] = 0.f;
    const int cg = tid & 15, bg = tid >> 4;
    const int lrow = tid & 63, kq = tid >> 6;

    for (int kc = 0; kc < 12; kc++) {
        __syncthreads();
        const float* wr = wv + (size_t)(n * 64 + lrow) * CC + kc * 64 + kq * 16;
        const float* ur = g_u + ((size_t)lrow * NH + n) * CC + kc * 64 + kq * 16;
        #pragma unroll
        for (int i = 0; i < 4; i++) {
            float4 w4 = *(const float4*)(wr + i * 4);
            float4 u4 = *(const float4*)(ur + i * 4);
            int k = kq * 16 + i * 4;
            swv[k + 0][lrow] = w4.x; swv[k + 1][lrow] = w4.y;
            swv[k + 2][lrow] = w4.z; swv[k + 3][lrow] = w4.w;
            su[k + 0][lrow] = u4.x; su[k + 1][lrow] = u4.y;
            su[k + 2][lrow] = u4.z; su[k + 3][lrow] = u4.w;
        }
        __syncthreads();
        #pragma unroll 4
        for (int k = 0; k < 64; k++) {
            float4 a4 = *(const float4*)&su[k][bg * 4];
            float4 b4 = *(const float4*)&swv[k][cg * 4];
            float av[4] = {a4.x, a4.y, a4.z, a4.w};
            float bvv[4] = {b4.x, b4.y, b4.z, b4.w};
            #pragma unroll
            for (int i = 0; i < 4; i++)
                #pragma unroll
                for (int j = 0; j < 4; j++)
                    acc[i][j] = fmaf(av[i], bvv[j], acc[i][j]);
        }
    }
    #pragma unroll
    for (int i = 0; i < 4; i++)
        #pragma unroll
        for (int j = 0; j < 4; j++) {
            int bmv = bg * 4 + i, c = cg * 4 + j;
            g_s[(size_t)bmv * CC + n * 64 + c] = acc[i][j] + bv[n * 64 + c] * sKt[bmv];
        }
}

// ---- ws[bm,n,j] = s[bm,n*64:].wp[j,n*64:] ; grid (12 jtiles x NH) ----
__global__ __launch_bounds__(256) void ws_kernel(const float* __restrict__ wp)
{
    __shared__ __align__(16) float wpp[64][68];
    __shared__ __align__(16) float ssm[64][68];
    const int j0 = blockIdx.x * 64, n = blockIdx.y, tid = threadIdx.x;
    for (int q = 0; q < 4; q++) {
        int u = q * 256 + tid;
        int r = u >> 4, e4 = u & 15;
        float4 v = *(const float4*)(wp + (size_t)(j0 + r) * CC + n * 64 + e4 * 4);
        wpp[e4 * 4 + 0][r] = v.x; wpp[e4 * 4 + 1][r] = v.y;
        wpp[e4 * 4 + 2][r] = v.z; wpp[e4 * 4 + 3][r] = v.w;
    }
    for (int q = 0; q < 4; q++) {
        int u = q * 256 + tid;
        int b = u >> 4, e4 = u & 15;
        float4 v = *(const float4*)(g_s + (size_t)b * CC + n * 64 + e4 * 4);
        ssm[e4 * 4 + 0][b] = v.x; ssm[e4 * 4 + 1][b] = v.y;
        ssm[e4 * 4 + 2][b] = v.z; ssm[e4 * 4 + 3][b] = v.w;
    }
    __syncthreads();
    const int tx = tid & 31, ty = tid >> 5;
    float acc[8][2];
    #pragma unroll
    for (int i = 0; i < 8; i++) { acc[i][0] = 0.f; acc[i][1] = 0.f; }
    #pragma unroll 4
    for (int e = 0; e < 64; e++) {
        float4 a0 = *(const float4*)&ssm[e][ty * 8];
        float4 a1 = *(const float4*)&ssm[e][ty * 8 + 4];
        float2 b2 = *(const float2*)&wpp[e][tx * 2];
        float av[8] = {a0.x, a0.y, a0.z, a0.w, a1.x, a1.y, a1.z, a1.w};
        #pragma unroll
        for (int i = 0; i < 8; i++) {
            acc[i][0] = fmaf(av[i], b2.x, acc[i][0]);
            acc[i][1] = fmaf(av[i], b2.y, acc[i][1]);
        }
    }
    #pragma unroll
    for (int i = 0; i < 8; i++) {
        int bmv = ty * 8 + i;
        g_ws[((size_t)bmv * NH + n) * CC + j0 + tx * 2 + 0] = acc[i][0];
        g_ws[((size_t)bmv * NH + n) * CC + j0 + tx * 2 + 1] = acc[i][1];
    }
}

// ---- out[bm,t,j] = sum_n z[n,t]*ws[n,j] + bp[j] ----
__global__ __launch_bounds__(256) void out_kernel(
    const float* __restrict__ bp, float* __restrict__ out)
{
    __shared__ __align__(16) float sws[NH][CC];
    __shared__ __align__(16) float sbp[CC];
    __shared__ float sz[NH][128];
    const int bm = blockIdx.y, t0 = blockIdx.x * 128, tid = threadIdx.x;
    for (int idx = tid; idx < NH * CC; idx += 256)
        sws[idx / CC][idx % CC] = g_ws[(size_t)bm * NH * CC + idx];
    for (int idx = tid; idx < CC; idx += 256) sbp[idx] = bp[idx];
    for (int idx = tid; idx < NH * 128; idx += 256)
        sz[idx >> 7][idx & 127] =
            g_z[((size_t)bm * NH + (idx >> 7)) * TT + t0 + (idx & 127)];
    __syncthreads();

    const int r = tid >> 1, half = tid & 1;
    float z[NH];
    #pragma unroll
    for (int n = 0; n < NH; n++) z[n] = sz[n][r];
    float4* out4 = (float4*)(out + ((size_t)bm * TT + t0 + r) * CC);
    const float4* bp4 = (const float4*)sbp;
    for (int k = 0; k < 96; k++) {
        int c4 = half * 96 + k;
        float4 acc = bp4[c4];
        #pragma unroll
        for (int n = 0; n < NH; n++) {
            float4 w = *(const float4*)&sws[n][c4 * 4];
            acc.x = fmaf(z[n], w.x, acc.x);
            acc.y = fmaf(z[n], w.y, acc.y);
            acc.z = fmaf(z[n], w.z, acc.z);
            acc.w = fmaf(z[n], w.w, acc.w);
        }
        out4[c4] = acc;
    }
}

// ---------------- host ----------------
extern "C" void kernel_launch(void* const* d_in, const int* in_sizes, int n_in,
                              void* d_out, int out_size)
{
    const float* x  = (const float*)d_in[0];
    const float* wq = (const float*)d_in[1];
    const float* bq = (const float*)d_in[2];
    const float* wk = (const float*)d_in[3];
    const float* bk = (const float*)d_in[4];
    const float* wv = (const float*)d_in[5];
    const float* bv = (const float*)d_in[6];
    const float* wp = (const float*)d_in[7];
    const float* bp = (const float*)d_in[8];
    float* out = (float*)d_out;

    cudaFuncSetAttribute(proj_mma, cudaFuncAttributeMaxDynamicSharedMemorySize, PROJ_SMEM);

    __half *xh, *wkh, *wqh;
    cudaGetSymbolAddress((void**)&xh, g_xh);
    cudaGetSymbolAddress((void**)&wkh, g_wh);
    wqh = wkh + CC * CC;

    const int n4x = RTOT * CC / 4;
    const int n4w = CC * CC / 4;
    conv_h<<<(n4x + 255) / 256, 256>>>((const float4*)x, (__half2*)xh, n4x);
    conv_h<<<(n4w + 255) / 256, 256>>>((const float4*)wk, (__half2*)wkh, n4w);
    conv_h<<<(n4w + 255) / 256, 256>>>((const float4*)wq, (__half2*)wqh, n4w);

    dim3 pg(3, 512);
    proj_mma<<<pg, 512, PROJ_SMEM>>>(xh, wkh, bk, 0);   // K -> kk, kpart
    reduce_ksum_kernel<<<(NBM * NH * DD + 255) / 256, 256>>>();
    u_kernel<<<dim3(6, NBM), 128>>>(x);
    s_kernel<<<NH, 256>>>(wv, bv);
    ws_kernel<<<dim3(12, NH), 256>>>(wp);
    proj_mma<<<pg, 512, PROJ_SMEM>>>(xh, wqh, bq, 1);   // Q -> z
    out_kernel<<<dim3(8, NBM), 256>>>(bp, out);
}

// round 9
// speedup vs baseline: 3.6528x; 1.0468x over previous
#include <cuda_runtime.h>
#include <cuda_fp16.h>
#include <math.h>
#include <stdint.h>

#define NBM 64
#define TT 1024
#define CC 768
#define NH 12
#define DD 64
#define EPSV 1e-6f
#define RTOT 65536

// ---- scratch (device globals; allocation-free contract) ----
__device__ __align__(1024) __half g_xh[RTOT * CC];
__device__ __align__(1024) __half g_wh[2][CC * CC];   // [0]=wk, [1]=wq
__device__ float g_kk  [NBM * NH * TT];
__device__ float g_kpart[NBM * NH * 8 * DD];
__device__ float g_ksum[NBM * NH * DD];
__device__ float g_u   [NBM * NH * CC];
__device__ float g_z   [NBM * NH * TT];
__device__ float g_s   [NBM * CC];
__device__ float g_ws  [NBM * NH * CC];

// ---------------- PTX helpers (base-target sm_80+) ----------------
__device__ __forceinline__ uint32_t smem_u32(const void* p) {
    uint32_t a;
    asm("{ .reg .u64 t; cvta.to.shared.u64 t, %1; cvt.u32.u64 %0, t; }" : "=r"(a) : "l"(p));
    return a;
}
__device__ __forceinline__ void cp16(uint32_t dst, const void* src) {
    asm volatile("cp.async.cg.shared.global [%0], [%1], 16;" :: "r"(dst), "l"(src));
}
__device__ __forceinline__ void cp_commit() {
    asm volatile("cp.async.commit_group;" ::: "memory");
}
__device__ __forceinline__ void cp_wait0() { asm volatile("cp.async.wait_group 0;" ::: "memory"); }
__device__ __forceinline__ void cp_wait1() { asm volatile("cp.async.wait_group 1;" ::: "memory"); }
__device__ __forceinline__ void ldm4(uint32_t* r, uint32_t addr) {
    asm volatile("ldmatrix.sync.aligned.m8n8.x4.shared.b16 {%0,%1,%2,%3}, [%4];"
        : "=r"(r[0]), "=r"(r[1]), "=r"(r[2]), "=r"(r[3]) : "r"(addr));
}
__device__ __forceinline__ void mma16816(float* c, const uint32_t* a, const uint32_t* b) {
    asm volatile(
        "mma.sync.aligned.m16n8k16.row.col.f32.f16.f16.f32 "
        "{%0,%1,%2,%3}, {%4,%5,%6,%7}, {%8,%9}, {%0,%1,%2,%3};"
        : "+f"(c[0]), "+f"(c[1]), "+f"(c[2]), "+f"(c[3])
        : "r"(a[0]), "r"(a[1]), "r"(a[2]), "r"(a[3]), "r"(b[0]), "r"(b[1]));
}

// ---------------- fp32 -> fp16 ----------------
__global__ __launch_bounds__(256) void conv_h(
    const float4* __restrict__ in, __half2* __restrict__ out, int n4)
{
    int i = blockIdx.x * blockDim.x + threadIdx.x;
    if (i >= n4) return;
    float4 v = in[i];
    out[2 * i]     = __floats2half2_rn(v.x, v.y);
    out[2 * i + 1] = __floats2half2_rn(v.z, v.w);
}

// ---------------- warp-MMA projection GEMM (single-pass fp16) ----------------
// CTA: 128 rows x 256 cols (4 heads), 16 warps (2x8) of 64x32 warp tiles,
// K-step 32, 3-stage cp.async ring, ONE __syncthreads per K-step.
// mode 0 (K): epilogue -> g_kk, g_kpart.  mode 1 (Q): epilogue -> g_z.
#define BK 32
#define STRIDE_B 80                   // 32 halfs (64B) + 16B pad
#define A_OFF 0
#define B_OFF 10240
#define STAGE_BYTES 30720
#define NSTAGE 3
#define PROJ_SMEM (NSTAGE * STAGE_BYTES)

__device__ __forceinline__ void load_stage(
    uint32_t st, const __half* a, const __half* b,
    int r0, int c0, int k0, int tid)
{
    {
        int row = tid >> 2, ch = tid & 3;
        cp16(st + A_OFF + row * STRIDE_B + ch * 16,
             a + (size_t)(r0 + row) * CC + k0 + ch * 8);
    }
    #pragma unroll
    for (int q = 0; q < 2; q++) {
        int u = q * 512 + tid;
        int row = u >> 2, ch = u & 3;
        cp16(st + B_OFF + row * STRIDE_B + ch * 16,
             b + (size_t)(c0 + row) * CC + k0 + ch * 8);
    }
}

__global__ __launch_bounds__(512, 1) void proj_mma(
    const __half* __restrict__ a, const __half* __restrict__ bw,
    const float* __restrict__ bias, int mode)
{
    extern __shared__ char sm[];
    __shared__ float sbias[256];
    __shared__ float sks[256];
    __shared__ float rowred[8][128];
    __shared__ float colred[2][8][32];

    const int tid = threadIdx.x;
    const int wid = tid >> 5, lane = tid & 31;
    const int warp_m = wid >> 3;          // 0..1 (64 rows)
    const int warp_n = wid & 7;           // 0..7 (32 cols)
    const int ct = blockIdx.x;            // 0..2 (4 heads each)
    const int ry = blockIdx.y;            // 0..511
    const int r0 = ry << 7, c0 = ct << 8;
    const int bm = ry >> 3, tl = ry & 7;
    const uint32_t sb = smem_u32(sm);

    if (tid < 256) {
        sbias[tid] = bias[c0 + tid];
        if (mode == 1)
            sks[tid] = g_ksum[((size_t)bm * NH + ct * 4 + (tid >> 6)) * DD + (tid & 63)];
    }

    float acc[4][4][4];
    #pragma unroll
    for (int mi = 0; mi < 4; mi++)
        #pragma unroll
        for (int ni = 0; ni < 4; ni++)
            #pragma unroll
            for (int r = 0; r < 4; r++) acc[mi][ni][r] = 0.f;

    const uint32_t aoff = (uint32_t)((lane & 15) * STRIDE_B + (lane >> 4) * 16);
    const uint32_t boff = (uint32_t)(((lane & 7) + ((lane >> 4) & 1) * 8) * STRIDE_B
                                     + ((lane >> 3) & 1) * 16);

    load_stage(sb, a, bw, r0, c0, 0, tid);
    cp_commit();
    load_stage(sb + STAGE_BYTES, a, bw, r0, c0, BK, tid);
    cp_commit();

    for (int ks = 0; ks < 24; ks++) {
        // stage ks ready? (groups 0..ks complete; ks+1 may pend)
        if (ks == 23) cp_wait0(); else cp_wait1();
        __syncthreads();   // all warps done reading stage ks-1; stage ks visible
        // safe now: stage (ks+2)%3 == (ks-1)%3, last read finished before sync
        if (ks + 2 < 24) {
            load_stage(sb + (uint32_t)(((ks + 2) % NSTAGE) * STAGE_BYTES),
                       a, bw, r0, c0, (ks + 2) * BK, tid);
            cp_commit();
        }

        const uint32_t st = sb + (uint32_t)((ks % NSTAGE) * STAGE_BYTES);
        #pragma unroll
        for (int kk = 0; kk < 2; kk++) {
            const uint32_t kb = (uint32_t)(kk * 32);
            uint32_t af[4][4], bf[2][4];
            #pragma unroll
            for (int mi = 0; mi < 4; mi++)
                ldm4(af[mi], st + A_OFF + (uint32_t)((warp_m * 64 + mi * 16) * STRIDE_B) + kb + aoff);
            #pragma unroll
            for (int ng = 0; ng < 2; ng++)
                ldm4(bf[ng], st + B_OFF + (uint32_t)((warp_n * 32 + ng * 16) * STRIDE_B) + kb + boff);
            #pragma unroll
            for (int mi = 0; mi < 4; mi++)
                #pragma unroll
                for (int ng = 0; ng < 2; ng++) {
                    mma16816(acc[mi][2 * ng],     af[mi], &bf[ng][0]);
                    mma16816(acc[mi][2 * ng + 1], af[mi], &bf[ng][2]);
                }
        }
    }

    // ---------------- fused epilogue ----------------
    const int cb = warp_n * 32 + 2 * (lane & 3);
    float colacc[4][2];
    #pragma unroll
    for (int ni = 0; ni < 4; ni++) { colacc[ni][0] = 0.f; colacc[ni][1] = 0.f; }

    #pragma unroll
    for (int mi = 0; mi < 4; mi++) {
        float rs0 = 0.f, rs1 = 0.f;
        #pragma unroll
        for (int ni = 0; ni < 4; ni++) {
            const float b0 = sbias[cb + ni * 8], b1 = sbias[cb + ni * 8 + 1];
            #pragma unroll
            for (int r = 0; r < 4; r++) {
                float pre = acc[mi][ni][r] + ((r & 1) ? b1 : b0);
                float v = (pre > 0.f) ? (pre + 1.f) : __expf(pre);
                if (mode == 0) {
                    colacc[ni][r & 1] += v;
                    if (r < 2) rs0 += v; else rs1 += v;
                } else {
                    float w = sks[cb + ni * 8 + (r & 1)];
                    if (r < 2) rs0 += v * w; else rs1 += v * w;
                }
            }
        }
        rs0 += __shfl_xor_sync(0xffffffffu, rs0, 1);
        rs0 += __shfl_xor_sync(0xffffffffu, rs0, 2);
        rs1 += __shfl_xor_sync(0xffffffffu, rs1, 1);
        rs1 += __shfl_xor_sync(0xffffffffu, rs1, 2);
        if ((lane & 3) == 0) {
            int row = warp_m * 64 + mi * 16 + (lane >> 2);
            rowred[warp_n][row]     = rs0;
            rowred[warp_n][row + 8] = rs1;
        }
    }

    if (mode == 0) {
        #pragma unroll
        for (int ni = 0; ni < 4; ni++)
            #pragma unroll
            for (int j = 0; j < 2; j++) {
                float c = colacc[ni][j];
                c += __shfl_xor_sync(0xffffffffu, c, 4);
                c += __shfl_xor_sync(0xffffffffu, c, 8);
                c += __shfl_xor_sync(0xffffffffu, c, 16);
                if (lane < 4)
                    colred[warp_m][warp_n][ni * 8 + lane * 2 + j] = c;
            }
    }
    __syncthreads();

    if (mode == 0) {
        {
            int hh = tid >> 7, row = tid & 127;
            float v = rowred[2 * hh][row] + rowred[2 * hh + 1][row];
            g_kk[((size_t)bm * NH + ct * 4 + hh) * TT + tl * 128 + row] = v;
        }
        if (tid < 256) {
            int wn = tid >> 5, c = tid & 31;
            int col = wn * 32 + c;
            int hh = col >> 6, d = col & 63;
            float v = colred[0][wn][c] + colred[1][wn][c];
            g_kpart[(((size_t)bm * NH + ct * 4 + hh) * 8 + tl) * DD + d] = v;
        }
    } else {
        int hh = tid >> 7, row = tid & 127;
        float sum = rowred[2 * hh][row] + rowred[2 * hh + 1][row];
        g_z[((size_t)bm * NH + ct * 4 + hh) * TT + tl * 128 + row] = 1.f / (sum + EPSV);
    }
}

// ---------------- ksum reduce ----------------
__global__ void reduce_ksum_kernel()
{
    int idx = blockIdx.x * blockDim.x + threadIdx.x;
    if (idx < NBM * NH * DD) {
        int hh = idx >> 6, d = idx & 63;
        float s = 0.f;
        #pragma unroll
        for (int p = 0; p < 8; p++)
            s += g_kpart[((size_t)hh * 8 + p) * DD + d];
        g_ksum[idx] = s;
    }
}

// ---- u[bm,n,c] = sum_t kk[bm,n,t] * xh[bm,t,c]  (fp16 x, half2 loads) ----
__global__ __launch_bounds__(128) void u_kernel()
{
    __shared__ float skk[NH][TT];
    const int bm = blockIdx.y, c0 = blockIdx.x * 256, tid = threadIdx.x;
    for (int idx = tid; idx < NH * TT; idx += 128)
        skk[idx >> 10][idx & 1023] = g_kk[(size_t)bm * NH * TT + idx];
    __syncthreads();
    float acc[NH][2];
    #pragma unroll
    for (int nn = 0; nn < NH; nn++) { acc[nn][0] = 0.f; acc[nn][1] = 0.f; }
    const __half* xp = g_xh + (size_t)bm * TT * CC + c0 + 2 * tid;
    for (int t = 0; t < TT; t++) {
        float2 xv = __half22float2(*(const __half2*)(xp + (size_t)t * CC));
        #pragma unroll
        for (int nn = 0; nn < NH; nn++) {
            float kv = skk[nn][t];
            acc[nn][0] = fmaf(kv, xv.x, acc[nn][0]);
            acc[nn][1] = fmaf(kv, xv.y, acc[nn][1]);
        }
    }
    #pragma unroll
    for (int nn = 0; nn < NH; nn++) {
        float* up = g_u + ((size_t)bm * NH + nn) * CC + c0 + 2 * tid;
        up[0] = acc[nn][0];
        up[1] = acc[nn][1];
    }
}

// ---- s[bm, n*64+c] = u[bm,n,:].wv[n*64+c,:] + bv[n*64+c]*Kt[bm,n] ----
// grid (NH, 4): 16 bm x 64 c per block.
__global__ __launch_bounds__(256) void s_kernel(
    const float* __restrict__ wv, const float* __restrict__ bv)
{
    __shared__ __align__(16) float swv[64][65];   // [k][c]
    __shared__ __align__(16) float su[64][17];    // [k][bm]
    __shared__ float sKt[16];
    const int n = blockIdx.x, bmg = blockIdx.y * 16, tid = threadIdx.x;
    if (tid < 16) {
        float s = 0.f;
        #pragma unroll
        for (int d = 0; d < DD; d++)
            s += g_ksum[((size_t)(bmg + tid) * NH + n) * DD + d];
        sKt[tid] = s;
    }
    const int c = tid & 63, bq = tid >> 6;
    float acc[4] = {0.f, 0.f, 0.f, 0.f};

    for (int kc = 0; kc < 12; kc++) {
        __syncthreads();
        // wv tile: 64 c-rows x 64 k, transposed into swv[k][c]
        {
            int row = tid >> 2, k16 = (tid & 3) * 16;
            const float* wr = wv + (size_t)(n * 64 + row) * CC + kc * 64 + k16;
            #pragma unroll
            for (int i = 0; i < 4; i++) {
                float4 v = *(const float4*)(wr + i * 4);
                swv[k16 + i * 4 + 0][row] = v.x; swv[k16 + i * 4 + 1][row] = v.y;
                swv[k16 + i * 4 + 2][row] = v.z; swv[k16 + i * 4 + 3][row] = v.w;
            }
        }
        // u tile: 16 bm x 64 k -> su[k][bm]
        {
            int row = tid >> 4, k4 = (tid & 15) * 4;
            float4 v = *(const float4*)(g_u + ((size_t)(bmg + row) * NH + n) * CC + kc * 64 + k4);
            su[k4 + 0][row] = v.x; su[k4 + 1][row] = v.y;
            su[k4 + 2][row] = v.z; su[k4 + 3][row] = v.w;
        }
        __syncthreads();
        #pragma unroll 8
        for (int k = 0; k < 64; k++) {
            float w = swv[k][c];
            #pragma unroll
            for (int i = 0; i < 4; i++)
                acc[i] = fmaf(su[k][bq * 4 + i], w, acc[i]);
        }
    }
    #pragma unroll
    for (int i = 0; i < 4; i++) {
        int bmv = bmg + bq * 4 + i;
        g_s[(size_t)bmv * CC + n * 64 + c] = acc[i] + bv[n * 64 + c] * sKt[bq * 4 + i];
    }
}

// ---- ws[bm,n,j] = s[bm,n*64:].wp[j,n*64:] ; grid (12 jtiles x NH) ----
__global__ __launch_bounds__(256) void ws_kernel(const float* __restrict__ wp)
{
    __shared__ __align__(16) float wpp[64][68];
    __shared__ __align__(16) float ssm[64][68];
    const int j0 = blockIdx.x * 64, n = blockIdx.y, tid = threadIdx.x;
    for (int q = 0; q < 4; q++) {
        int u = q * 256 + tid;
        int r = u >> 4, e4 = u & 15;
        float4 v = *(const float4*)(wp + (size_t)(j0 + r) * CC + n * 64 + e4 * 4);
        wpp[e4 * 4 + 0][r] = v.x; wpp[e4 * 4 + 1][r] = v.y;
        wpp[e4 * 4 + 2][r] = v.z; wpp[e4 * 4 + 3][r] = v.w;
    }
    for (int q = 0; q < 4; q++) {
        int u = q * 256 + tid;
        int b = u >> 4, e4 = u & 15;
        float4 v = *(const float4*)(g_s + (size_t)b * CC + n * 64 + e4 * 4);
        ssm[e4 * 4 + 0][b] = v.x; ssm[e4 * 4 + 1][b] = v.y;
        ssm[e4 * 4 + 2][b] = v.z; ssm[e4 * 4 + 3][b] = v.w;
    }
    __syncthreads();
    const int tx = tid & 31, ty = tid >> 5;
    float acc[8][2];
    #pragma unroll
    for (int i = 0; i < 8; i++) { acc[i][0] = 0.f; acc[i][1] = 0.f; }
    #pragma unroll 4
    for (int e = 0; e < 64; e++) {
        float4 a0 = *(const float4*)&ssm[e][ty * 8];
        float4 a1 = *(const float4*)&ssm[e][ty * 8 + 4];
        float2 b2 = *(const float2*)&wpp[e][tx * 2];
        float av[8] = {a0.x, a0.y, a0.z, a0.w, a1.x, a1.y, a1.z, a1.w};
        #pragma unroll
        for (int i = 0; i < 8; i++) {
            acc[i][0] = fmaf(av[i], b2.x, acc[i][0]);
            acc[i][1] = fmaf(av[i], b2.y, acc[i][1]);
        }
    }
    #pragma unroll
    for (int i = 0; i < 8; i++) {
        int bmv = ty * 8 + i;
        g_ws[((size_t)bmv * NH + n) * CC + j0 + tx * 2 + 0] = acc[i][0];
        g_ws[((size_t)bmv * NH + n) * CC + j0 + tx * 2 + 1] = acc[i][1];
    }
}

// ---- out[bm,t,j] = sum_n z[n,t]*ws[n,j] + bp[j] ----
__global__ __launch_bounds__(256) void out_kernel(
    const float* __restrict__ bp, float* __restrict__ out)
{
    __shared__ __align__(16) float sws[NH][CC];
    __shared__ __align__(16) float sbp[CC];
    __shared__ float sz[NH][128];
    const int bm = blockIdx.y, t0 = blockIdx.x * 128, tid = threadIdx.x;
    for (int idx = tid; idx < NH * CC; idx += 256)
        sws[idx / CC][idx % CC] = g_ws[(size_t)bm * NH * CC + idx];
    for (int idx = tid; idx < CC; idx += 256) sbp[idx] = bp[idx];
    for (int idx = tid; idx < NH * 128; idx += 256)
        sz[idx >> 7][idx & 127] =
            g_z[((size_t)bm * NH + (idx >> 7)) * TT + t0 + (idx & 127)];
    __syncthreads();

    const int r = tid >> 1, half = tid & 1;
    float z[NH];
    #pragma unroll
    for (int n = 0; n < NH; n++) z[n] = sz[n][r];
    float4* out4 = (float4*)(out + ((size_t)bm * TT + t0 + r) * CC);
    const float4* bp4 = (const float4*)sbp;
    for (int k = 0; k < 96; k++) {
        int c4 = half * 96 + k;
        float4 acc = bp4[c4];
        #pragma unroll
        for (int n = 0; n < NH; n++) {
            float4 w = *(const float4*)&sws[n][c4 * 4];
            acc.x = fmaf(z[n], w.x, acc.x);
            acc.y = fmaf(z[n], w.y, acc.y);
            acc.z = fmaf(z[n], w.z, acc.z);
            acc.w = fmaf(z[n], w.w, acc.w);
        }
        out4[c4] = acc;
    }
}

// ---------------- host ----------------
extern "C" void kernel_launch(void* const* d_in, const int* in_sizes, int n_in,
                              void* d_out, int out_size)
{
    const float* x  = (const float*)d_in[0];
    const float* wq = (const float*)d_in[1];
    const float* bq = (const float*)d_in[2];
    const float* wk = (const float*)d_in[3];
    const float* bk = (const float*)d_in[4];
    const float* wv = (const float*)d_in[5];
    const float* bv = (const float*)d_in[6];
    const float* wp = (const float*)d_in[7];
    const float* bp = (const float*)d_in[8];
    float* out = (float*)d_out;

    cudaFuncSetAttribute(proj_mma, cudaFuncAttributeMaxDynamicSharedMemorySize, PROJ_SMEM);

    __half *xh, *wkh, *wqh;
    cudaGetSymbolAddress((void**)&xh, g_xh);
    cudaGetSymbolAddress((void**)&wkh, g_wh);
    wqh = wkh + CC * CC;

    const int n4x = RTOT * CC / 4;
    const int n4w = CC * CC / 4;
    conv_h<<<(n4x + 255) / 256, 256>>>((const float4*)x, (__half2*)xh, n4x);
    conv_h<<<(n4w + 255) / 256, 256>>>((const float4*)wk, (__half2*)wkh, n4w);
    conv_h<<<(n4w + 255) / 256, 256>>>((const float4*)wq, (__half2*)wqh, n4w);

    dim3 pg(3, 512);
    proj_mma<<<pg, 512, PROJ_SMEM>>>(xh, wkh, bk, 0);   // K -> kk, kpart
    reduce_ksum_kernel<<<(NBM * NH * DD + 255) / 256, 256>>>();
    u_kernel<<<dim3(3, NBM), 128>>>();
    s_kernel<<<dim3(NH, 4), 256>>>(wv, bv);
    ws_kernel<<<dim3(12, NH), 256>>>(wp);
    proj_mma<<<pg, 512, PROJ_SMEM>>>(xh, wqh, bq, 1);   // Q -> z
    out_kernel<<<dim3(8, NBM), 256>>>(bp, out);
}

// round 10
// speedup vs baseline: 3.8749x; 1.0608x over previous
#include <cuda_runtime.h>
#include <cuda_fp16.h>
#include <math.h>
#include <stdint.h>

#define NBM 64
#define TT 1024
#define CC 768
#define NH 12
#define DD 64
#define EPSV 1e-6f
#define RTOT 65536

// ---- scratch (device globals; allocation-free contract) ----
__device__ __align__(1024) __half g_xh[RTOT * CC];
__device__ __align__(1024) __half g_wh[2][CC * CC];   // [0]=wk, [1]=wq
__device__ float g_kk  [NBM * NH * TT];
__device__ float g_kpart[NBM * NH * 8 * DD];
__device__ float g_ksum[NBM * NH * DD];
__device__ float g_u   [NBM * NH * CC];
__device__ float g_z   [NBM * NH * TT];
__device__ float g_s   [NBM * CC];
__device__ float g_ws  [NBM * NH * CC];

// ---------------- PTX helpers (base-target sm_80+) ----------------
__device__ __forceinline__ uint32_t smem_u32(const void* p) {
    uint32_t a;
    asm("{ .reg .u64 t; cvta.to.shared.u64 t, %1; cvt.u32.u64 %0, t; }" : "=r"(a) : "l"(p));
    return a;
}
__device__ __forceinline__ void cp16(uint32_t dst, const void* src) {
    asm volatile("cp.async.cg.shared.global [%0], [%1], 16;" :: "r"(dst), "l"(src));
}
__device__ __forceinline__ void cp_commit() {
    asm volatile("cp.async.commit_group;" ::: "memory");
}
__device__ __forceinline__ void cp_wait4() { asm volatile("cp.async.wait_group 4;" ::: "memory"); }
__device__ __forceinline__ void ldm4(uint32_t* r, uint32_t addr) {
    asm volatile("ldmatrix.sync.aligned.m8n8.x4.shared.b16 {%0,%1,%2,%3}, [%4];"
        : "=r"(r[0]), "=r"(r[1]), "=r"(r[2]), "=r"(r[3]) : "r"(addr));
}
__device__ __forceinline__ void mma16816(float* c, const uint32_t* a, const uint32_t* b) {
    asm volatile(
        "mma.sync.aligned.m16n8k16.row.col.f32.f16.f16.f32 "
        "{%0,%1,%2,%3}, {%4,%5,%6,%7}, {%8,%9}, {%0,%1,%2,%3};"
        : "+f"(c[0]), "+f"(c[1]), "+f"(c[2]), "+f"(c[3])
        : "r"(a[0]), "r"(a[1]), "r"(a[2]), "r"(a[3]), "r"(b[0]), "r"(b[1]));
}

// ---------------- fp32 -> fp16 ----------------
__global__ __launch_bounds__(256) void conv_h(
    const float4* __restrict__ in, __half2* __restrict__ out, int n4)
{
    int i = blockIdx.x * blockDim.x + threadIdx.x;
    if (i >= n4) return;
    float4 v = in[i];
    out[2 * i]     = __floats2half2_rn(v.x, v.y);
    out[2 * i + 1] = __floats2half2_rn(v.z, v.w);
}

// ---------------- warp-MMA projection GEMM (single-pass fp16) ----------------
// CTA: 128 rows x 256 cols (4 heads), 16 warps (2x8) of 64x32 warp tiles,
// K-step 32, SIX-stage cp.async ring (prefetch distance 5 covers DRAM latency),
// one __syncthreads per K-step, one commit per iteration (empty in tail) so
// wait_group 4 always retires exactly stage ks.
// mode 0 (K): epilogue -> g_kk, g_kpart.  mode 1 (Q): epilogue -> g_z.
#define BK 32
#define STRIDE_B 80                   // 32 halfs (64B) + 16B pad
#define A_OFF 0
#define B_OFF 10240
#define STAGE_BYTES 30720
#define NSTAGE 6
#define KSTEPS 24
#define PROJ_SMEM (NSTAGE * STAGE_BYTES)

__device__ __forceinline__ void load_stage(
    uint32_t st, const __half* a, const __half* b,
    int r0, int c0, int k0, int tid)
{
    {
        int row = tid >> 2, ch = tid & 3;
        cp16(st + A_OFF + row * STRIDE_B + ch * 16,
             a + (size_t)(r0 + row) * CC + k0 + ch * 8);
    }
    #pragma unroll
    for (int q = 0; q < 2; q++) {
        int u = q * 512 + tid;
        int row = u >> 2, ch = u & 3;
        cp16(st + B_OFF + row * STRIDE_B + ch * 16,
             b + (size_t)(c0 + row) * CC + k0 + ch * 8);
    }
}

__global__ __launch_bounds__(512, 1) void proj_mma(
    const __half* __restrict__ a, const __half* __restrict__ bw,
    const float* __restrict__ bias, int mode)
{
    extern __shared__ char sm[];
    __shared__ float sbias[256];
    __shared__ float sks[256];
    __shared__ float rowred[8][128];
    __shared__ float colred[2][8][32];

    const int tid = threadIdx.x;
    const int wid = tid >> 5, lane = tid & 31;
    const int warp_m = wid >> 3;          // 0..1 (64 rows)
    const int warp_n = wid & 7;           // 0..7 (32 cols)
    const int ct = blockIdx.x;            // 0..2 (4 heads each)
    const int ry = blockIdx.y;            // 0..511
    const int r0 = ry << 7, c0 = ct << 8;
    const int bm = ry >> 3, tl = ry & 7;
    const uint32_t sb = smem_u32(sm);

    if (tid < 256) {
        sbias[tid] = bias[c0 + tid];
        if (mode == 1)
            sks[tid] = g_ksum[((size_t)bm * NH + ct * 4 + (tid >> 6)) * DD + (tid & 63)];
    }

    float acc[4][4][4];
    #pragma unroll
    for (int mi = 0; mi < 4; mi++)
        #pragma unroll
        for (int ni = 0; ni < 4; ni++)
            #pragma unroll
            for (int r = 0; r < 4; r++) acc[mi][ni][r] = 0.f;

    const uint32_t aoff = (uint32_t)((lane & 15) * STRIDE_B + (lane >> 4) * 16);
    const uint32_t boff = (uint32_t)(((lane & 7) + ((lane >> 4) & 1) * 8) * STRIDE_B
                                     + ((lane >> 3) & 1) * 16);

    // prologue: stages 0..4 in flight (5 groups)
    #pragma unroll
    for (int s = 0; s < NSTAGE - 1; s++) {
        load_stage(sb + (uint32_t)(s * STAGE_BYTES), a, bw, r0, c0, s * BK, tid);
        cp_commit();
    }

    for (int ks = 0; ks < KSTEPS; ks++) {
        // commits so far = 5 + ks; keep <=4 outstanding -> group ks retired
        cp_wait4();
        __syncthreads();   // all warps finished reading stage ks-1 (lives in (ks+5)%6)
        if (ks + NSTAGE - 1 < KSTEPS)
            load_stage(sb + (uint32_t)(((ks + NSTAGE - 1) % NSTAGE) * STAGE_BYTES),
                       a, bw, r0, c0, (ks + NSTAGE - 1) * BK, tid);
        cp_commit();       // real or empty: exactly one group per iteration

        const uint32_t st = sb + (uint32_t)((ks % NSTAGE) * STAGE_BYTES);
        #pragma unroll
        for (int kk = 0; kk < 2; kk++) {
            const uint32_t kb = (uint32_t)(kk * 32);
            uint32_t af[4][4], bf[2][4];
            #pragma unroll
            for (int mi = 0; mi < 4; mi++)
                ldm4(af[mi], st + A_OFF + (uint32_t)((warp_m * 64 + mi * 16) * STRIDE_B) + kb + aoff);
            #pragma unroll
            for (int ng = 0; ng < 2; ng++)
                ldm4(bf[ng], st + B_OFF + (uint32_t)((warp_n * 32 + ng * 16) * STRIDE_B) + kb + boff);
            #pragma unroll
            for (int mi = 0; mi < 4; mi++)
                #pragma unroll
                for (int ng = 0; ng < 2; ng++) {
                    mma16816(acc[mi][2 * ng],     af[mi], &bf[ng][0]);
                    mma16816(acc[mi][2 * ng + 1], af[mi], &bf[ng][2]);
                }
        }
    }

    // ---------------- fused epilogue ----------------
    const int cb = warp_n * 32 + 2 * (lane & 3);
    float colacc[4][2];
    #pragma unroll
    for (int ni = 0; ni < 4; ni++) { colacc[ni][0] = 0.f; colacc[ni][1] = 0.f; }

    #pragma unroll
    for (int mi = 0; mi < 4; mi++) {
        float rs0 = 0.f, rs1 = 0.f;
        #pragma unroll
        for (int ni = 0; ni < 4; ni++) {
            const float b0 = sbias[cb + ni * 8], b1 = sbias[cb + ni * 8 + 1];
            #pragma unroll
            for (int r = 0; r < 4; r++) {
                float pre = acc[mi][ni][r] + ((r & 1) ? b1 : b0);
                float v = (pre > 0.f) ? (pre + 1.f) : __expf(pre);
                if (mode == 0) {
                    colacc[ni][r & 1] += v;
                    if (r < 2) rs0 += v; else rs1 += v;
                } else {
                    float w = sks[cb + ni * 8 + (r & 1)];
                    if (r < 2) rs0 += v * w; else rs1 += v * w;
                }
            }
        }
        rs0 += __shfl_xor_sync(0xffffffffu, rs0, 1);
        rs0 += __shfl_xor_sync(0xffffffffu, rs0, 2);
        rs1 += __shfl_xor_sync(0xffffffffu, rs1, 1);
        rs1 += __shfl_xor_sync(0xffffffffu, rs1, 2);
        if ((lane & 3) == 0) {
            int row = warp_m * 64 + mi * 16 + (lane >> 2);
            rowred[warp_n][row]     = rs0;
            rowred[warp_n][row + 8] = rs1;
        }
    }

    if (mode == 0) {
        #pragma unroll
        for (int ni = 0; ni < 4; ni++)
            #pragma unroll
            for (int j = 0; j < 2; j++) {
                float c = colacc[ni][j];
                c += __shfl_xor_sync(0xffffffffu, c, 4);
                c += __shfl_xor_sync(0xffffffffu, c, 8);
                c += __shfl_xor_sync(0xffffffffu, c, 16);
                if (lane < 4)
                    colred[warp_m][warp_n][ni * 8 + lane * 2 + j] = c;
            }
    }
    __syncthreads();

    if (mode == 0) {
        {
            int hh = tid >> 7, row = tid & 127;
            float v = rowred[2 * hh][row] + rowred[2 * hh + 1][row];
            g_kk[((size_t)bm * NH + ct * 4 + hh) * TT + tl * 128 + row] = v;
        }
        if (tid < 256) {
            int wn = tid >> 5, c = tid & 31;
            int col = wn * 32 + c;
            int hh = col >> 6, d = col & 63;
            float v = colred[0][wn][c] + colred[1][wn][c];
            g_kpart[(((size_t)bm * NH + ct * 4 + hh) * 8 + tl) * DD + d] = v;
        }
    } else {
        int hh = tid >> 7, row = tid & 127;
        float sum = rowred[2 * hh][row] + rowred[2 * hh + 1][row];
        g_z[((size_t)bm * NH + ct * 4 + hh) * TT + tl * 128 + row] = 1.f / (sum + EPSV);
    }
}

// ---------------- ksum reduce ----------------
__global__ void reduce_ksum_kernel()
{
    int idx = blockIdx.x * blockDim.x + threadIdx.x;
    if (idx < NBM * NH * DD) {
        int hh = idx >> 6, d = idx & 63;
        float s = 0.f;
        #pragma unroll
        for (int p = 0; p < 8; p++)
            s += g_kpart[((size_t)hh * 8 + p) * DD + d];
        g_ksum[idx] = s;
    }
}

// ---- u[bm,n,c] = sum_t kk[bm,n,t] * xh[bm,t,c]  (fp16 x, half2 loads) ----
__global__ __launch_bounds__(128) void u_kernel()
{
    __shared__ float skk[NH][TT];
    const int bm = blockIdx.y, c0 = blockIdx.x * 256, tid = threadIdx.x;
    for (int idx = tid; idx < NH * TT; idx += 128)
        skk[idx >> 10][idx & 1023] = g_kk[(size_t)bm * NH * TT + idx];
    __syncthreads();
    float acc[NH][2];
    #pragma unroll
    for (int nn = 0; nn < NH; nn++) { acc[nn][0] = 0.f; acc[nn][1] = 0.f; }
    const __half* xp = g_xh + (size_t)bm * TT * CC + c0 + 2 * tid;
    for (int t = 0; t < TT; t++) {
        float2 xv = __half22float2(*(const __half2*)(xp + (size_t)t * CC));
        #pragma unroll
        for (int nn = 0; nn < NH; nn++) {
            float kv = skk[nn][t];
            acc[nn][0] = fmaf(kv, xv.x, acc[nn][0]);
            acc[nn][1] = fmaf(kv, xv.y, acc[nn][1]);
        }
    }
    #pragma unroll
    for (int nn = 0; nn < NH; nn++) {
        float* up = g_u + ((size_t)bm * NH + nn) * CC + c0 + 2 * tid;
        up[0] = acc[nn][0];
        up[1] = acc[nn][1];
    }
}

// ---- s[bm, n*64+c] = u[bm,n,:].wv[n*64+c,:] + bv[n*64+c]*Kt[bm,n] ----
__global__ __launch_bounds__(256) void s_kernel(
    const float* __restrict__ wv, const float* __restrict__ bv)
{
    __shared__ __align__(16) float swv[64][65];   // [k][c]
    __shared__ __align__(16) float su[64][17];    // [k][bm]
    __shared__ float sKt[16];
    const int n = blockIdx.x, bmg = blockIdx.y * 16, tid = threadIdx.x;
    if (tid < 16) {
        float s = 0.f;
        #pragma unroll
        for (int d = 0; d < DD; d++)
            s += g_ksum[((size_t)(bmg + tid) * NH + n) * DD + d];
        sKt[tid] = s;
    }
    const int c = tid & 63, bq = tid >> 6;
    float acc[4] = {0.f, 0.f, 0.f, 0.f};

    for (int kc = 0; kc < 12; kc++) {
        __syncthreads();
        {
            int row = tid >> 2, k16 = (tid & 3) * 16;
            const float* wr = wv + (size_t)(n * 64 + row) * CC + kc * 64 + k16;
            #pragma unroll
            for (int i = 0; i < 4; i++) {
                float4 v = *(const float4*)(wr + i * 4);
                swv[k16 + i * 4 + 0][row] = v.x; swv[k16 + i * 4 + 1][row] = v.y;
                swv[k16 + i * 4 + 2][row] = v.z; swv[k16 + i * 4 + 3][row] = v.w;
            }
        }
        {
            int row = tid >> 4, k4 = (tid & 15) * 4;
            float4 v = *(const float4*)(g_u + ((size_t)(bmg + row) * NH + n) * CC + kc * 64 + k4);
            su[k4 + 0][row] = v.x; su[k4 + 1][row] = v.y;
            su[k4 + 2][row] = v.z; su[k4 + 3][row] = v.w;
        }
        __syncthreads();
        #pragma unroll 8
        for (int k = 0; k < 64; k++) {
            float w = swv[k][c];
            #pragma unroll
            for (int i = 0; i < 4; i++)
                acc[i] = fmaf(su[k][bq * 4 + i], w, acc[i]);
        }
    }
    #pragma unroll
    for (int i = 0; i < 4; i++) {
        int bmv = bmg + bq * 4 + i;
        g_s[(size_t)bmv * CC + n * 64 + c] = acc[i] + bv[n * 64 + c] * sKt[bq * 4 + i];
    }
}

// ---- ws[bm,n,j] = s[bm,n*64:].wp[j,n*64:] ; grid (12 jtiles x NH) ----
__global__ __launch_bounds__(256) void ws_kernel(const float* __restrict__ wp)
{
    __shared__ __align__(16) float wpp[64][68];
    __shared__ __align__(16) float ssm[64][68];
    const int j0 = blockIdx.x * 64, n = blockIdx.y, tid = threadIdx.x;
    for (int q = 0; q < 4; q++) {
        int u = q * 256 + tid;
        int r = u >> 4, e4 = u & 15;
        float4 v = *(const float4*)(wp + (size_t)(j0 + r) * CC + n * 64 + e4 * 4);
        wpp[e4 * 4 + 0][r] = v.x; wpp[e4 * 4 + 1][r] = v.y;
        wpp[e4 * 4 + 2][r] = v.z; wpp[e4 * 4 + 3][r] = v.w;
    }
    for (int q = 0; q < 4; q++) {
        int u = q * 256 + tid;
        int b = u >> 4, e4 = u & 15;
        float4 v = *(const float4*)(g_s + (size_t)b * CC + n * 64 + e4 * 4);
        ssm[e4 * 4 + 0][b] = v.x; ssm[e4 * 4 + 1][b] = v.y;
        ssm[e4 * 4 + 2][b] = v.z; ssm[e4 * 4 + 3][b] = v.w;
    }
    __syncthreads();
    const int tx = tid & 31, ty = tid >> 5;
    float acc[8][2];
    #pragma unroll
    for (int i = 0; i < 8; i++) { acc[i][0] = 0.f; acc[i][1] = 0.f; }
    #pragma unroll 4
    for (int e = 0; e < 64; e++) {
        float4 a0 = *(const float4*)&ssm[e][ty * 8];
        float4 a1 = *(const float4*)&ssm[e][ty * 8 + 4];
        float2 b2 = *(const float2*)&wpp[e][tx * 2];
        float av[8] = {a0.x, a0.y, a0.z, a0.w, a1.x, a1.y, a1.z, a1.w};
        #pragma unroll
        for (int i = 0; i < 8; i++) {
            acc[i][0] = fmaf(av[i], b2.x, acc[i][0]);
            acc[i][1] = fmaf(av[i], b2.y, acc[i][1]);
        }
    }
    #pragma unroll
    for (int i = 0; i < 8; i++) {
        int bmv = ty * 8 + i;
        g_ws[((size_t)bmv * NH + n) * CC + j0 + tx * 2 + 0] = acc[i][0];
        g_ws[((size_t)bmv * NH + n) * CC + j0 + tx * 2 + 1] = acc[i][1];
    }
}

// ---- out[bm,t,j] = sum_n z[n,t]*ws[n,j] + bp[j] ----
__global__ __launch_bounds__(256) void out_kernel(
    const float* __restrict__ bp, float* __restrict__ out)
{
    __shared__ __align__(16) float sws[NH][CC];
    __shared__ __align__(16) float sbp[CC];
    __shared__ float sz[NH][128];
    const int bm = blockIdx.y, t0 = blockIdx.x * 128, tid = threadIdx.x;
    for (int idx = tid; idx < NH * CC; idx += 256)
        sws[idx / CC][idx % CC] = g_ws[(size_t)bm * NH * CC + idx];
    for (int idx = tid; idx < CC; idx += 256) sbp[idx] = bp[idx];
    for (int idx = tid; idx < NH * 128; idx += 256)
        sz[idx >> 7][idx & 127] =
            g_z[((size_t)bm * NH + (idx >> 7)) * TT + t0 + (idx & 127)];
    __syncthreads();

    const int r = tid >> 1, half = tid & 1;
    float z[NH];
    #pragma unroll
    for (int n = 0; n < NH; n++) z[n] = sz[n][r];
    float4* out4 = (float4*)(out + ((size_t)bm * TT + t0 + r) * CC);
    const float4* bp4 = (const float4*)sbp;
    for (int k = 0; k < 96; k++) {
        int c4 = half * 96 + k;
        float4 acc = bp4[c4];
        #pragma unroll
        for (int n = 0; n < NH; n++) {
            float4 w = *(const float4*)&sws[n][c4 * 4];
            acc.x = fmaf(z[n], w.x, acc.x);
            acc.y = fmaf(z[n], w.y, acc.y);
            acc.z = fmaf(z[n], w.z, acc.z);
            acc.w = fmaf(z[n], w.w, acc.w);
        }
        out4[c4] = acc;
    }
}

// ---------------- host ----------------
extern "C" void kernel_launch(void* const* d_in, const int* in_sizes, int n_in,
                              void* d_out, int out_size)
{
    const float* x  = (const float*)d_in[0];
    const float* wq = (const float*)d_in[1];
    const float* bq = (const float*)d_in[2];
    const float* wk = (const float*)d_in[3];
    const float* bk = (const float*)d_in[4];
    const float* wv = (const float*)d_in[5];
    const float* bv = (const float*)d_in[6];
    const float* wp = (const float*)d_in[7];
    const float* bp = (const float*)d_in[8];
    float* out = (float*)d_out;

    cudaFuncSetAttribute(proj_mma, cudaFuncAttributeMaxDynamicSharedMemorySize, PROJ_SMEM);

    __half *xh, *wkh, *wqh;
    cudaGetSymbolAddress((void**)&xh, g_xh);
    cudaGetSymbolAddress((void**)&wkh, g_wh);
    wqh = wkh + CC * CC;

    const int n4x = RTOT * CC / 4;
    const int n4w = CC * CC / 4;
    conv_h<<<(n4x + 255) / 256, 256>>>((const float4*)x, (__half2*)xh, n4x);
    conv_h<<<(n4w + 255) / 256, 256>>>((const float4*)wk, (__half2*)wkh, n4w);
    conv_h<<<(n4w + 255) / 256, 256>>>((const float4*)wq, (__half2*)wqh, n4w);

    dim3 pg(3, 512);
    proj_mma<<<pg, 512, PROJ_SMEM>>>(xh, wkh, bk, 0);   // K -> kk, kpart
    reduce_ksum_kernel<<<(NBM * NH * DD + 255) / 256, 256>>>();
    u_kernel<<<dim3(3, NBM), 128>>>();
    s_kernel<<<dim3(NH, 4), 256>>>(wv, bv);
    ws_kernel<<<dim3(12, NH), 256>>>(wp);
    proj_mma<<<pg, 512, PROJ_SMEM>>>(xh, wqh, bq, 1);   // Q -> z
    out_kernel<<<dim3(8, NBM), 256>>>(bp, out);
}